// round 1
// baseline (speedup 1.0000x reference)
#include <cuda_runtime.h>
#include <cstdint>

// Problem dims (fixed by the reference): B=16, Ci=Co=64, S=256, m1=m2=32
#define NB 16
#define NC 64
#define NS 256
#define NKY 32
#define NF 63   // frequencies -31..31 along x

// ---------------- device scratch (no allocs allowed) ----------------
__device__ __align__(16) float2 g_tab[264];                       // padded cos/sin table
__device__ __align__(16) float2 g_W [63*32*64*64];                // [f][ky][i][o]
__device__ __align__(16) float2 g_X1[16*64*256*32];               // [b][i][x][ky]
__device__ __align__(16) float2 g_X2[63*32*16*64];                // [f][ky][b][i]
__device__ __align__(16) float2 g_X3[16*64*63*32];                // [b][o][f][ky]
__device__ __align__(16) float2 g_Y1[16*64*256*32];               // [b][o][x][ky]

// bank-conflict-avoiding pad for the 256-entry twiddle table
__device__ __forceinline__ int tp(int i) { return i + (i >> 5); }

// ---------------- init: twiddle table ----------------
__global__ void sc_tab() {
    int t = threadIdx.x;
    if (t < 264) {
        int k = t / 33;
        int idx = t - k;               // inverse of tp() (duplicates in pad holes are harmless)
        float ang = (float)(6.283185307179586 * (double)idx / 256.0);
        g_tab[t] = make_float2(cosf(ang), sinf(ang));
    }
}

// ---------------- init: build complex weights W[i][o][f][ky] -> layout [f][ky][i][o] ----------------
__global__ void sc_build_w(const float* __restrict__ y0r, const float* __restrict__ y0i,
                           const float* __restrict__ ypr, const float* __restrict__ ypi,
                           const float* __restrict__ w00) {
    int t = blockIdx.x * 256 + threadIdx.x;
    if (t >= 63 * 32 * 64 * 64) return;
    int o  = t & 63;
    int i  = (t >> 6) & 63;
    int ky = (t >> 12) & 31;
    int f  = t >> 17;                  // 0..62
    int io = i * 64 + o;
    float wr, wi;
    if (ky == 0) {
        if (f < 31)       { wr = y0r[io * 31 + f];        wi = y0i[io * 31 + f]; }
        else if (f == 31) { wr = w00[io];                 wi = 0.f; }
        else              { wr = y0r[io * 31 + (62 - f)]; wi = -y0i[io * 31 + (62 - f)]; }
    } else {
        int idx = (io * 63 + f) * 31 + (ky - 1);
        wr = ypr[idx]; wi = ypi[idx];
    }
    g_W[((f * 32 + ky) * 64 + i) * 64 + o] = make_float2(wr, wi);
}

// ---------------- K1: DFT along y (256 real -> 32 complex), even/odd symmetry ----------------
// block: 32 rows, 256 threads. thread = (rowgroup of 4, ky)
#define SMEM1 (264*8 + 127*32*8 + 32*257*4)
__global__ void sc_k1(const float* __restrict__ x) {
    extern __shared__ float sm[];
    float2* stab = (float2*)sm;                 // 264
    float2* seo  = stab + 264;                  // [s-1][row] : 127*32
    float*  sx   = (float*)(seo + 127 * 32);    // [row][257]
    int tid = threadIdx.x, bid = blockIdx.x;

    for (int q = tid; q < 264; q += 256) stab[q] = g_tab[q];
    const float* gx = x + (size_t)bid * 8192;
    for (int q = tid; q < 8192; q += 256) {
        int r = q >> 8, c = q & 255;
        sx[r * 257 + c] = gx[q];
    }
    __syncthreads();
    for (int e = tid; e < 127 * 32; e += 256) {
        int row = e & 31, s = (e >> 5) + 1;
        float a = sx[row * 257 + s], b = sx[row * 257 + 256 - s];
        seo[e] = make_float2(a + b, a - b);
    }
    __syncthreads();

    int ky = tid & 31, r0 = (tid >> 5) * 4;
    float sgn = (ky & 1) ? -1.f : 1.f;
    float re[4], im[4];
#pragma unroll
    for (int r = 0; r < 4; r++) {
        re[r] = sx[(r0 + r) * 257] + sgn * sx[(r0 + r) * 257 + 128];
        im[r] = 0.f;
    }
    int p = 0;
#pragma unroll 4
    for (int s = 1; s < 128; s++) {
        p = (p + ky) & 255;            // p = ky*s mod 256
        float2 t = stab[tp(p)];
        const float4* eo4 = (const float4*)(seo + (s - 1) * 32 + r0);
        float4 ab = eo4[0], cd = eo4[1];
        re[0] += ab.x * t.x;  im[0] -= ab.y * t.y;
        re[1] += ab.z * t.x;  im[1] -= ab.w * t.y;
        re[2] += cd.x * t.x;  im[2] -= cd.y * t.y;
        re[3] += cd.z * t.x;  im[3] -= cd.w * t.y;
    }
    const float SC = 1.f / 256.f;      // forward ortho (both axes folded here)
#pragma unroll
    for (int r = 0; r < 4; r++)
        g_X1[(size_t)(bid * 32 + r0 + r) * 32 + ky] = make_float2(re[r] * SC, im[r] * SC);
}

// ---------------- K2: DFT along x (256 -> 63), +/-f pairing ----------------
// block per (b,i). thread = (fbase, ky); each thread does 4 f values.
#define SMEM2 (264*8 + 8192*8)
__global__ void sc_k2() {
    extern __shared__ float sm[];
    float2* stab = (float2*)sm;            // 264
    float2* sX1  = stab + 264;             // [x][ky] : 8192
    int tid = threadIdx.x, bid = blockIdx.x;

    for (int q = tid; q < 264; q += 256) stab[q] = g_tab[q];
    {
        const float4* src = (const float4*)(g_X1 + (size_t)bid * 8192);
        float4* dst = (float4*)sX1;
        for (int q = tid; q < 4096; q += 256) dst[q] = src[q];
    }
    __syncthreads();

    int ky = tid & 31, fb = tid >> 5;
    int b = bid >> 6, i = bid & 63;
    int bi = b * 64 + i;
#pragma unroll
    for (int jj = 0; jj < 4; jj++) {
        int fq = fb + 8 * jj;              // 0..31
        float Ac = 0.f, As = 0.f, Bc = 0.f, Bs = 0.f;
        int p = 0;
#pragma unroll 4
        for (int xx = 0; xx < 256; xx++) {
            float2 t = stab[tp(p)];
            float2 v = sX1[xx * 32 + ky];
            Ac += v.x * t.x; As += v.x * t.y;
            Bc += v.y * t.x; Bs += v.y * t.y;
            p = (p + fq) & 255;
        }
        g_X2[(size_t)((31 + fq) * 32 + ky) * 1024 + bi] = make_float2(Ac + Bs, Bc - As);
        if (fq > 0)
            g_X2[(size_t)((31 - fq) * 32 + ky) * 1024 + bi] = make_float2(Ac - Bs, Bc + As);
    }
}

// ---------------- K3: channel mix, block per (f,ky) ----------------
__global__ void sc_k3() {
    __shared__ __align__(16) float2 sW[4096];     // [i][o]
    __shared__ __align__(16) float2 sX[1024];     // [b][i]
    int tid = threadIdx.x, bid = blockIdx.x;      // bid = f*32+ky
    {
        const float4* srcW = (const float4*)(g_W + (size_t)bid * 4096);
        float4* dW = (float4*)sW;
        for (int q = tid; q < 2048; q += 256) dW[q] = srcW[q];
        const float4* srcX = (const float4*)(g_X2 + (size_t)bid * 1024);
        float4* dX = (float4*)sX;
        for (int q = tid; q < 512; q += 256) dX[q] = srcX[q];
    }
    __syncthreads();

    int o4 = (tid & 15) * 4, b = tid >> 4;
    float ar0 = 0, ai0 = 0, ar1 = 0, ai1 = 0, ar2 = 0, ai2 = 0, ar3 = 0, ai3 = 0;
#pragma unroll 4
    for (int i = 0; i < 64; i++) {
        float2 v = sX[b * 64 + i];
        const float4* wp = (const float4*)(sW + i * 64 + o4);
        float4 w01 = wp[0], w23 = wp[1];
        ar0 += v.x * w01.x - v.y * w01.y;  ai0 += v.x * w01.y + v.y * w01.x;
        ar1 += v.x * w01.z - v.y * w01.w;  ai1 += v.x * w01.w + v.y * w01.z;
        ar2 += v.x * w23.x - v.y * w23.y;  ai2 += v.x * w23.y + v.y * w23.x;
        ar3 += v.x * w23.z - v.y * w23.w;  ai3 += v.x * w23.w + v.y * w23.z;
    }
    size_t base = (size_t)(b * 64 + o4) * 2016 + bid;
    g_X3[base]          = make_float2(ar0, ai0);
    g_X3[base + 2016]   = make_float2(ar1, ai1);
    g_X3[base + 2*2016] = make_float2(ar2, ai2);
    g_X3[base + 3*2016] = make_float2(ar3, ai3);
}

// ---------------- K4: inverse DFT along x (63 -> 256), U/V pairing ----------------
__global__ void sc_k4() {
    __shared__ __align__(16) float2 sX3[2016];
    __shared__ __align__(16) float2 sU[992], sV[992];   // [fq-1][ky]
    __shared__ __align__(16) float2 stab[264];
    int tid = threadIdx.x, bid = blockIdx.x;            // bid = b*64+o
    {
        const float4* src = (const float4*)(g_X3 + (size_t)bid * 2016);
        float4* dst = (float4*)sX3;
        for (int q = tid; q < 1008; q += 256) dst[q] = src[q];
        for (int q = tid; q < 264; q += 256) stab[q] = g_tab[q];
    }
    __syncthreads();
    for (int e = tid; e < 992; e += 256) {
        int ky = e & 31, fq = (e >> 5) + 1;
        float2 P = sX3[(31 + fq) * 32 + ky];
        float2 Q = sX3[(31 - fq) * 32 + ky];
        sU[e] = make_float2(P.x + Q.x, P.y + Q.y);
        sV[e] = make_float2(-(P.y - Q.y), P.x - Q.x);   // i*(P-Q)
    }
    __syncthreads();

    int ky4 = (tid & 7) * 4, xs = tid >> 3;
    for (int xi = 0; xi < 8; xi++) {
        int xx = xs + 32 * xi;
        const float4* m = (const float4*)(sX3 + 31 * 32 + ky4);
        float4 m01 = m[0], m23 = m[1];
        float a0x = m01.x, a0y = m01.y, a1x = m01.z, a1y = m01.w;
        float a2x = m23.x, a2y = m23.y, a3x = m23.z, a3y = m23.w;
        int p = 0;
#pragma unroll 4
        for (int fq = 1; fq < 32; fq++) {
            p = (p + xx) & 255;                 // p = fq*xx
            float2 t = stab[tp(p)];
            const float4* up = (const float4*)(sU + (fq - 1) * 32 + ky4);
            const float4* vp = (const float4*)(sV + (fq - 1) * 32 + ky4);
            float4 u01 = up[0], u23 = up[1], v01 = vp[0], v23 = vp[1];
            a0x += t.x * u01.x + t.y * v01.x;  a0y += t.x * u01.y + t.y * v01.y;
            a1x += t.x * u01.z + t.y * v01.z;  a1y += t.x * u01.w + t.y * v01.w;
            a2x += t.x * u23.x + t.y * v23.x;  a2y += t.x * u23.y + t.y * v23.y;
            a3x += t.x * u23.z + t.y * v23.z;  a3y += t.x * u23.w + t.y * v23.w;
        }
        float4* out = (float4*)(g_Y1 + (size_t)bid * 8192 + xx * 32 + ky4);
        out[0] = make_float4(a0x, a0y, a1x, a1y);
        out[1] = make_float4(a2x, a2y, a3x, a3y);
    }
}

// ---------------- K5: irfft along y (32 modes -> 256 real), mirror pairing ----------------
__global__ void sc_k5(float* __restrict__ out) {
    __shared__ __align__(16) float2 sY[512];    // [row(16)][ky(32)] scaled
    __shared__ __align__(16) float2 stab[264];
    int tid = threadIdx.x, bid = blockIdx.x;    // 16 rows per block
    for (int q = tid; q < 264; q += 256) stab[q] = g_tab[q];
    {
        const float4* src = (const float4*)(g_Y1 + (size_t)bid * 512);
        float4 v = src[tid];                    // row = tid>>4, ky0 = 2*(tid&15)
        int ky0 = 2 * (tid & 15);
        const float SC = 1.f / 256.f;           // inverse ortho (both axes)
        float s0 = (ky0 == 0) ? SC : 2.f * SC;
        sY[2 * tid]     = make_float2(v.x * s0, v.y * s0);
        sY[2 * tid + 1] = make_float2(v.z * 2.f * SC, v.w * 2.f * SC);
    }
    __syncthreads();

    int t = tid & 31, rp = tid >> 5;
    int row0 = 2 * rp, row1 = row0 + 1;
    size_t ob0 = ((size_t)bid * 16 + row0) * 256;
    size_t ob1 = ((size_t)bid * 16 + row1) * 256;
    for (int j = 0; j < 5; j++) {
        int s = t + 32 * j;
        if (s > 128) break;
        float A0 = 0, SB0 = 0, A1 = 0, SB1 = 0;
        int p = 0;
#pragma unroll 4
        for (int ky = 0; ky < 32; ky += 2) {
            float2 t0 = stab[tp(p)];
            int p1 = (p + s) & 255;
            float2 t1 = stab[tp(p1)];
            float4 v0 = *(const float4*)(sY + row0 * 32 + ky);
            float4 v1 = *(const float4*)(sY + row1 * 32 + ky);
            A0  += v0.x * t0.x + v0.z * t1.x;
            SB0 += v0.y * t0.y + v0.w * t1.y;
            A1  += v1.x * t0.x + v1.z * t1.x;
            SB1 += v1.y * t0.y + v1.w * t1.y;
            p = (p1 + s) & 255;
        }
        out[ob0 + s] = A0 - SB0;
        out[ob1 + s] = A1 - SB1;
        if (s >= 1 && s <= 127) {
            out[ob0 + 256 - s] = A0 + SB0;
            out[ob1 + 256 - s] = A1 + SB1;
        }
    }
}

// ---------------- launch ----------------
extern "C" void kernel_launch(void* const* d_in, const int* in_sizes, int n_in,
                              void* d_out, int out_size) {
    const float* x   = (const float*)d_in[0];
    const float* y0r = (const float*)d_in[1];
    const float* y0i = (const float*)d_in[2];
    const float* ypr = (const float*)d_in[3];
    const float* ypi = (const float*)d_in[4];
    const float* w00 = (const float*)d_in[5];
    float* out = (float*)d_out;

    cudaFuncSetAttribute(sc_k1, cudaFuncAttributeMaxDynamicSharedMemorySize, SMEM1);
    cudaFuncSetAttribute(sc_k2, cudaFuncAttributeMaxDynamicSharedMemorySize, SMEM2);

    sc_tab<<<1, 264>>>();
    sc_build_w<<<(63 * 32 * 64 * 64 + 255) / 256, 256>>>(y0r, y0i, ypr, ypi, w00);
    sc_k1<<<8192, 256, SMEM1>>>(x);     // 262144 rows / 32
    sc_k2<<<1024, 256, SMEM2>>>();      // per (b,i)
    sc_k3<<<2016, 256>>>();             // per (f,ky)
    sc_k4<<<1024, 256>>>();             // per (b,o)
    sc_k5<<<16384, 256>>>(out);         // 262144 rows / 16
}

// round 2
// speedup vs baseline: 1.2532x; 1.2532x over previous
#include <cuda_runtime.h>
#include <cstdint>

// Problem dims (fixed): B=16, Ci=Co=64, S=256, m1=m2=32
// ---------------- device scratch (no allocs allowed) ----------------
__device__ __align__(16) float2 g_tab[264];                       // padded cos/sin table
__device__ __align__(16) float2 g_tw1[127*32];                    // [s-1][ky] twiddles for K1
__device__ __align__(16) float2 g_tw5[32*132];                    // [ky][s] scaled twiddles for K5
__device__ __align__(16) float2 g_W [63*32*64*64];                // [f][ky][i][o]
__device__ __align__(16) float2 g_X1[16*64*256*32];               // [b][i][x][ky]
__device__ __align__(16) float2 g_X2[63*32*16*64];                // [f][ky][b][i]
__device__ __align__(16) float2 g_X3[16*64*63*32];                // [b][o][f][ky]
__device__ __align__(16) float2 g_Y1[16*64*256*32];               // [b][o][x][ky]

__device__ __forceinline__ int tp(int i) { return i + (i >> 5); }

// ---------------- init: all tables ----------------
__global__ void sc_tabs() {
    int t = blockIdx.x * 256 + threadIdx.x;
    if (t < 264) {
        int k = t / 33;
        int idx = t - k;
        float ang = (float)(6.283185307179586 * (double)idx / 256.0);
        g_tab[t] = make_float2(cosf(ang), sinf(ang));
    }
    int e1 = t - 264;
    if (e1 >= 0 && e1 < 127 * 32) {
        int s = (e1 >> 5) + 1, ky = e1 & 31;
        double ang = 6.283185307179586 * (double)(ky * s % 256) / 256.0;
        g_tw1[e1] = make_float2((float)cos(ang), (float)sin(ang));
    }
    int e2 = t - 264 - 127 * 32;
    if (e2 >= 0 && e2 < 32 * 132) {
        int ky = e2 / 132, s = e2 % 132;
        if (s <= 128) {
            double ang = 6.283185307179586 * (double)((s * ky) % 256) / 256.0;
            float sc = (ky == 0 ? 1.f : 2.f) / 256.f;
            g_tw5[e2] = make_float2(sc * (float)cos(ang), sc * (float)sin(ang));
        } else {
            g_tw5[e2] = make_float2(0.f, 0.f);
        }
    }
}

// ---------------- build W: ky=0 plane (small, 63*4096 elems) ----------------
__global__ void sc_build_w0(const float* __restrict__ y0r, const float* __restrict__ y0i,
                            const float* __restrict__ w00) {
    int t = blockIdx.x * 256 + threadIdx.x;
    if (t >= 63 * 4096) return;
    int io = t & 4095;
    int f  = t >> 12;
    float wr, wi;
    if (f < 31)       { wr = y0r[io * 31 + f];        wi = y0i[io * 31 + f]; }
    else if (f == 31) { wr = w00[io];                 wi = 0.f; }
    else              { wr = y0r[io * 31 + (62 - f)]; wi = -y0i[io * 31 + (62 - f)]; }
    g_W[(size_t)(f * 32) * 4096 + io] = make_float2(wr, wi);
}

// ---------------- build W: ky>=1 planes via tiled transpose ----------------
// source M[io][fk] with fk = f*31 + (ky-1), io = i*64+o ; dst g_W[(f*32+ky)*4096 + io]
__global__ void sc_build_wt(const float* __restrict__ ypr, const float* __restrict__ ypi) {
    __shared__ float2 tile[32][33];
    int tx = threadIdx.x, ty = threadIdx.y;        // 32 x 8
    int fk0 = blockIdx.x * 32, io0 = blockIdx.y * 32;
#pragma unroll
    for (int k = 0; k < 4; k++) {
        int io = io0 + ty + 8 * k;
        int fk = fk0 + tx;
        if (fk < 1953)
            tile[ty + 8 * k][tx] = make_float2(ypr[(size_t)io * 1953 + fk],
                                               ypi[(size_t)io * 1953 + fk]);
    }
    __syncthreads();
#pragma unroll
    for (int k = 0; k < 4; k++) {
        int fk = fk0 + ty + 8 * k;
        if (fk < 1953) {
            int f  = fk / 31;
            int ky = fk - f * 31 + 1;
            g_W[(size_t)(f * 32 + ky) * 4096 + io0 + tx] = tile[tx][ty + 8 * k];
        }
    }
}

// ---------------- K1: DFT along y (256 real -> 32 complex), conflict-free twiddles ----
#define SMEM1 (127*32*8 + 127*32*8 + 32*257*4)
__global__ void sc_k1(const float* __restrict__ x) {
    extern __shared__ float sm[];
    float2* stw  = (float2*)sm;                 // [s-1][ky] : 127*32
    float2* seo  = stw + 127 * 32;              // [s-1][row] : 127*32
    float*  sx   = (float*)(seo + 127 * 32);    // [row][257]
    int tid = threadIdx.x, bid = blockIdx.x;

    {
        const float4* src = (const float4*)g_tw1;
        float4* dst = (float4*)stw;
        for (int q = tid; q < 2032; q += 256) dst[q] = src[q];
    }
    const float* gx = x + (size_t)bid * 8192;
    for (int q = tid; q < 8192; q += 256) {
        int r = q >> 8, c = q & 255;
        sx[r * 257 + c] = gx[q];
    }
    __syncthreads();
    for (int e = tid; e < 127 * 32; e += 256) {
        int row = e & 31, s = (e >> 5) + 1;
        float a = sx[row * 257 + s], b = sx[row * 257 + 256 - s];
        seo[e] = make_float2(a + b, a - b);
    }
    __syncthreads();

    int ky = tid & 31, r0 = (tid >> 5) * 4;
    float sgn = (ky & 1) ? -1.f : 1.f;
    float re[4], im[4];
#pragma unroll
    for (int r = 0; r < 4; r++) {
        re[r] = sx[(r0 + r) * 257] + sgn * sx[(r0 + r) * 257 + 128];
        im[r] = 0.f;
    }
#pragma unroll 4
    for (int s = 1; s < 128; s++) {
        float2 t = stw[(s - 1) * 32 + ky];                     // lanes consecutive: no conflict
        const float4* eo4 = (const float4*)(seo + (s - 1) * 32 + r0);  // warp-uniform: broadcast
        float4 ab = eo4[0], cd = eo4[1];
        re[0] += ab.x * t.x;  im[0] -= ab.y * t.y;
        re[1] += ab.z * t.x;  im[1] -= ab.w * t.y;
        re[2] += cd.x * t.x;  im[2] -= cd.y * t.y;
        re[3] += cd.z * t.x;  im[3] -= cd.w * t.y;
    }
    const float SC = 1.f / 256.f;
#pragma unroll
    for (int r = 0; r < 4; r++)
        g_X1[(size_t)(bid * 32 + r0 + r) * 32 + ky] = make_float2(re[r] * SC, im[r] * SC);
}

// ---------------- K2: DFT along x (256 -> 63), 4 freqs per thread ----------------
#define SMEM2 (264*8 + 8192*8)
__global__ void sc_k2() {
    extern __shared__ float sm[];
    float2* stab = (float2*)sm;            // 264
    float2* sX1  = stab + 264;             // [x][ky] : 8192
    int tid = threadIdx.x, bid = blockIdx.x;

    for (int q = tid; q < 264; q += 256) stab[q] = g_tab[q];
    {
        const float4* src = (const float4*)(g_X1 + (size_t)bid * 8192);
        float4* dst = (float4*)sX1;
        for (int q = tid; q < 4096; q += 256) dst[q] = src[q];
    }
    __syncthreads();

    int ky = tid & 31, g = tid >> 5;
    int b = bid >> 6, i = bid & 63;
    int bi = b * 64 + i;
    int f0 = g, f1 = g + 8, f2 = g + 16, f3 = g + 24;
    float Ac0=0,As0=0,Bc0=0,Bs0=0, Ac1=0,As1=0,Bc1=0,Bs1=0;
    float Ac2=0,As2=0,Bc2=0,Bs2=0, Ac3=0,As3=0,Bc3=0,Bs3=0;
    int p0 = 0, p1 = 0, p2 = 0, p3 = 0;
#pragma unroll 4
    for (int xx = 0; xx < 256; xx++) {
        float2 v = sX1[xx * 32 + ky];
        float2 t;
        t = stab[tp(p0)]; Ac0 += v.x*t.x; As0 += v.x*t.y; Bc0 += v.y*t.x; Bs0 += v.y*t.y; p0 = (p0 + f0) & 255;
        t = stab[tp(p1)]; Ac1 += v.x*t.x; As1 += v.x*t.y; Bc1 += v.y*t.x; Bs1 += v.y*t.y; p1 = (p1 + f1) & 255;
        t = stab[tp(p2)]; Ac2 += v.x*t.x; As2 += v.x*t.y; Bc2 += v.y*t.x; Bs2 += v.y*t.y; p2 = (p2 + f2) & 255;
        t = stab[tp(p3)]; Ac3 += v.x*t.x; As3 += v.x*t.y; Bc3 += v.y*t.x; Bs3 += v.y*t.y; p3 = (p3 + f3) & 255;
    }
#define K2OUT(FQ, AC, AS, BC, BS)                                                        \
    g_X2[(size_t)((31 + (FQ)) * 32 + ky) * 1024 + bi] = make_float2((AC)+(BS), (BC)-(AS)); \
    if ((FQ) > 0)                                                                        \
        g_X2[(size_t)((31 - (FQ)) * 32 + ky) * 1024 + bi] = make_float2((AC)-(BS), (BC)+(AS));
    K2OUT(f0, Ac0, As0, Bc0, Bs0)
    K2OUT(f1, Ac1, As1, Bc1, Bs1)
    K2OUT(f2, Ac2, As2, Bc2, Bs2)
    K2OUT(f3, Ac3, As3, Bc3, Bs3)
#undef K2OUT
}

// ---------------- K3: channel mix, block per (f,ky) ----------------
__global__ void sc_k3() {
    __shared__ __align__(16) float2 sW[4096];     // [i][o]
    __shared__ __align__(16) float2 sX[1024];     // [b][i]
    int tid = threadIdx.x, bid = blockIdx.x;      // bid = f*32+ky
    {
        const float4* srcW = (const float4*)(g_W + (size_t)bid * 4096);
        float4* dW = (float4*)sW;
        for (int q = tid; q < 2048; q += 256) dW[q] = srcW[q];
        const float4* srcX = (const float4*)(g_X2 + (size_t)bid * 1024);
        float4* dX = (float4*)sX;
        for (int q = tid; q < 512; q += 256) dX[q] = srcX[q];
    }
    __syncthreads();

    int o4 = (tid & 15) * 4, b = tid >> 4;
    float ar0 = 0, ai0 = 0, ar1 = 0, ai1 = 0, ar2 = 0, ai2 = 0, ar3 = 0, ai3 = 0;
#pragma unroll 4
    for (int i = 0; i < 64; i++) {
        float2 v = sX[b * 64 + i];
        const float4* wp = (const float4*)(sW + i * 64 + o4);
        float4 w01 = wp[0], w23 = wp[1];
        ar0 += v.x * w01.x - v.y * w01.y;  ai0 += v.x * w01.y + v.y * w01.x;
        ar1 += v.x * w01.z - v.y * w01.w;  ai1 += v.x * w01.w + v.y * w01.z;
        ar2 += v.x * w23.x - v.y * w23.y;  ai2 += v.x * w23.y + v.y * w23.x;
        ar3 += v.x * w23.z - v.y * w23.w;  ai3 += v.x * w23.w + v.y * w23.z;
    }
    size_t base = (size_t)(b * 64 + o4) * 2016 + bid;
    g_X3[base]          = make_float2(ar0, ai0);
    g_X3[base + 2016]   = make_float2(ar1, ai1);
    g_X3[base + 2*2016] = make_float2(ar2, ai2);
    g_X3[base + 3*2016] = make_float2(ar3, ai3);
}

// ---------------- K4: inverse DFT along x (63 -> 256), U/V pairing ----------------
__global__ void sc_k4() {
    __shared__ __align__(16) float2 sX3[2016];
    __shared__ __align__(16) float2 sU[992], sV[992];   // [fq-1][ky]
    __shared__ __align__(16) float2 stab[264];
    int tid = threadIdx.x, bid = blockIdx.x;            // bid = b*64+o
    {
        const float4* src = (const float4*)(g_X3 + (size_t)bid * 2016);
        float4* dst = (float4*)sX3;
        for (int q = tid; q < 1008; q += 256) dst[q] = src[q];
        for (int q = tid; q < 264; q += 256) stab[q] = g_tab[q];
    }
    __syncthreads();
    for (int e = tid; e < 992; e += 256) {
        int ky = e & 31, fq = (e >> 5) + 1;
        float2 P = sX3[(31 + fq) * 32 + ky];
        float2 Q = sX3[(31 - fq) * 32 + ky];
        sU[e] = make_float2(P.x + Q.x, P.y + Q.y);
        sV[e] = make_float2(-(P.y - Q.y), P.x - Q.x);   // i*(P-Q)
    }
    __syncthreads();

    int ky4 = (tid & 7) * 4, xs = tid >> 3;
    for (int xi = 0; xi < 8; xi++) {
        int xx = xs + 32 * xi;
        const float4* m = (const float4*)(sX3 + 31 * 32 + ky4);
        float4 m01 = m[0], m23 = m[1];
        float a0x = m01.x, a0y = m01.y, a1x = m01.z, a1y = m01.w;
        float a2x = m23.x, a2y = m23.y, a3x = m23.z, a3y = m23.w;
        int p = 0;
#pragma unroll 4
        for (int fq = 1; fq < 32; fq++) {
            p = (p + xx) & 255;
            float2 t = stab[tp(p)];
            const float4* up = (const float4*)(sU + (fq - 1) * 32 + ky4);
            const float4* vp = (const float4*)(sV + (fq - 1) * 32 + ky4);
            float4 u01 = up[0], u23 = up[1], v01 = vp[0], v23 = vp[1];
            a0x += t.x * u01.x + t.y * v01.x;  a0y += t.x * u01.y + t.y * v01.y;
            a1x += t.x * u01.z + t.y * v01.z;  a1y += t.x * u01.w + t.y * v01.w;
            a2x += t.x * u23.x + t.y * v23.x;  a2y += t.x * u23.y + t.y * v23.y;
            a3x += t.x * u23.z + t.y * v23.z;  a3y += t.x * u23.w + t.y * v23.w;
        }
        float4* out = (float4*)(g_Y1 + (size_t)bid * 8192 + xx * 32 + ky4);
        out[0] = make_float4(a0x, a0y, a1x, a1y);
        out[1] = make_float4(a2x, a2y, a3x, a3y);
    }
}

// ---------------- K5: irfft along y, conflict-free twiddles, 4s x 4rows blocking ----
__global__ void sc_k5(float* __restrict__ out) {
    __shared__ __align__(16) float2 sY[1024];       // [row(32)][ky(32)] raw
    __shared__ __align__(16) float2 stw[32*132];    // [ky][s] scaled twiddles
    int tid = threadIdx.x, bid = blockIdx.x;        // 32 rows per block, grid 8192
    {
        const float4* src = (const float4*)(g_Y1 + (size_t)bid * 1024);
        float4* dst = (float4*)sY;
        dst[tid]       = src[tid];
        dst[tid + 256] = src[tid + 256];
    }
    {
        const float4* src = (const float4*)g_tw5;
        float4* dst = (float4*)stw;
        for (int q = tid; q < 2112; q += 256) dst[q] = src[q];
    }
    __syncthreads();

    int l = tid & 31, w = tid >> 5, r0 = 4 * w;
    float A0[4]={0,0,0,0}, S0[4]={0,0,0,0};
    float A1[4]={0,0,0,0}, S1[4]={0,0,0,0};
    float A2[4]={0,0,0,0}, S2[4]={0,0,0,0};
    float A3[4]={0,0,0,0}, S3[4]={0,0,0,0};
#pragma unroll 2
    for (int ky = 0; ky < 32; ky++) {
        float2 t0 = stw[ky * 132 + l];          // lanes consecutive: no conflict
        float2 t1 = stw[ky * 132 + l + 32];
        float2 t2 = stw[ky * 132 + l + 64];
        float2 t3 = stw[ky * 132 + l + 96];
#pragma unroll
        for (int r = 0; r < 4; r++) {
            float2 v = sY[(r0 + r) * 32 + ky];  // warp-uniform: broadcast
            A0[r] += v.x * t0.x;  S0[r] += v.y * t0.y;
            A1[r] += v.x * t1.x;  S1[r] += v.y * t1.y;
            A2[r] += v.x * t2.x;  S2[r] += v.y * t2.y;
            A3[r] += v.x * t3.x;  S3[r] += v.y * t3.y;
        }
    }
#pragma unroll
    for (int r = 0; r < 4; r++) {
        size_t ob = ((size_t)bid * 32 + r0 + r) * 256;
        int s0 = l;
        out[ob + s0] = A0[r] - S0[r];
        if (s0 > 0) out[ob + 256 - s0] = A0[r] + S0[r];
        out[ob + l + 32]  = A1[r] - S1[r];
        out[ob + 224 - l] = A1[r] + S1[r];
        out[ob + l + 64]  = A2[r] - S2[r];
        out[ob + 192 - l] = A2[r] + S2[r];
        out[ob + l + 96]  = A3[r] - S3[r];
        out[ob + 160 - l] = A3[r] + S3[r];
    }
    // s = 128 column (Nyquist along x-output axis)
    if (tid < 32) {
        int row = tid;
        float a = 0.f;
#pragma unroll 4
        for (int ky = 0; ky < 32; ky++)
            a += sY[row * 32 + ky].x * stw[ky * 132 + 128].x;
        out[((size_t)bid * 32 + row) * 256 + 128] = a;
    }
}

// ---------------- launch ----------------
extern "C" void kernel_launch(void* const* d_in, const int* in_sizes, int n_in,
                              void* d_out, int out_size) {
    const float* x   = (const float*)d_in[0];
    const float* y0r = (const float*)d_in[1];
    const float* y0i = (const float*)d_in[2];
    const float* ypr = (const float*)d_in[3];
    const float* ypi = (const float*)d_in[4];
    const float* w00 = (const float*)d_in[5];
    float* out = (float*)d_out;

    cudaFuncSetAttribute(sc_k1, cudaFuncAttributeMaxDynamicSharedMemorySize, SMEM1);
    cudaFuncSetAttribute(sc_k2, cudaFuncAttributeMaxDynamicSharedMemorySize, SMEM2);

    sc_tabs<<<34, 256>>>();
    sc_build_w0<<<(63 * 4096 + 255) / 256, 256>>>(y0r, y0i, w00);
    sc_build_wt<<<dim3(62, 128), dim3(32, 8)>>>(ypr, ypi);
    sc_k1<<<8192, 256, SMEM1>>>(x);
    sc_k2<<<1024, 256, SMEM2>>>();
    sc_k3<<<2016, 256>>>();
    sc_k4<<<1024, 256>>>();
    sc_k5<<<8192, 256>>>(out);
}

// round 3
// speedup vs baseline: 1.8866x; 1.5055x over previous
#include <cuda_runtime.h>
#include <cstdint>

// Problem dims (fixed): B=16, Ci=Co=64, S=256, m1=m2=32
// ---------------- device scratch (no allocs allowed) ----------------
__device__ __align__(16) float2 g_tab[264];                       // padded cos/sin table (K2,K4)
__device__ __align__(16) float2 g_tw1[63*32];                     // [s-1][ky] twiddles for K1 (s=1..63)
__device__ __align__(16) float2 g_tw5[32*64];                     // [ky][s] scaled twiddles for K5 (s=0..63)
__device__ __align__(16) float2 g_W [63*32*64*64];                // [f][ky][i][o]
__device__ __align__(16) float2 g_X1[16*64*256*32];               // [b][i][x][ky]
__device__ __align__(16) float2 g_X2[63*32*16*64];                // [f][ky][b][i]
__device__ __align__(16) float2 g_X3[16*64*63*32];                // [b][o][f][ky]
__device__ __align__(16) float2 g_Y1[16*64*256*32];               // [b][o][x][ky]

__device__ __forceinline__ int tp(int i) { return i + (i >> 5); }

// ---------------- init: all tables ----------------
__global__ void sc_tabs() {
    int t = blockIdx.x * 256 + threadIdx.x;
    if (t < 264) {
        int k = t / 33;
        int idx = t - k;
        float ang = (float)(6.283185307179586 * (double)idx / 256.0);
        g_tab[t] = make_float2(cosf(ang), sinf(ang));
    }
    int e1 = t - 264;
    if (e1 >= 0 && e1 < 63 * 32) {
        int s = (e1 >> 5) + 1, ky = e1 & 31;           // s = 1..63
        double ang = 6.283185307179586 * (double)((ky * s) % 256) / 256.0;
        g_tw1[e1] = make_float2((float)cos(ang), (float)sin(ang));
    }
    int e2 = t - 264 - 63 * 32;
    if (e2 >= 0 && e2 < 32 * 64) {
        int ky = e2 >> 6, s = e2 & 63;                 // s = 0..63
        double ang = 6.283185307179586 * (double)((s * ky) % 256) / 256.0;
        float sc = (ky == 0 ? 1.f : 2.f) / 256.f;
        g_tw5[e2] = make_float2(sc * (float)cos(ang), sc * (float)sin(ang));
    }
}

// ---------------- build W: ky=0 plane ----------------
__global__ void sc_build_w0(const float* __restrict__ y0r, const float* __restrict__ y0i,
                            const float* __restrict__ w00) {
    int t = blockIdx.x * 256 + threadIdx.x;
    if (t >= 63 * 4096) return;
    int io = t & 4095;
    int f  = t >> 12;
    float wr, wi;
    if (f < 31)       { wr = y0r[io * 31 + f];        wi = y0i[io * 31 + f]; }
    else if (f == 31) { wr = w00[io];                 wi = 0.f; }
    else              { wr = y0r[io * 31 + (62 - f)]; wi = -y0i[io * 31 + (62 - f)]; }
    g_W[(size_t)(f * 32) * 4096 + io] = make_float2(wr, wi);
}

// ---------------- build W: ky>=1 planes via tiled transpose ----------------
__global__ void sc_build_wt(const float* __restrict__ ypr, const float* __restrict__ ypi) {
    __shared__ float2 tile[32][33];
    int tx = threadIdx.x, ty = threadIdx.y;        // 32 x 8
    int fk0 = blockIdx.x * 32, io0 = blockIdx.y * 32;
#pragma unroll
    for (int k = 0; k < 4; k++) {
        int io = io0 + ty + 8 * k;
        int fk = fk0 + tx;
        if (fk < 1953)
            tile[ty + 8 * k][tx] = make_float2(ypr[(size_t)io * 1953 + fk],
                                               ypi[(size_t)io * 1953 + fk]);
    }
    __syncthreads();
#pragma unroll
    for (int k = 0; k < 4; k++) {
        int fk = fk0 + ty + 8 * k;
        if (fk < 1953) {
            int f  = fk / 31;
            int ky = fk - f * 31 + 1;
            g_W[(size_t)(f * 32 + ky) * 4096 + io0 + tx] = tile[tx][ty + 8 * k];
        }
    }
}

// ---------------- K1: DFT along y (256 real -> 32 complex), double fold ----------------
// Re[ky] = x0 + s*x128 + E64*c64 + sum_{s=1}^{63} (E[s] + sgn*E[128-s]) cos
// Im[ky] = -O64*s64 - sum_{s=1}^{63} (O[s] - sgn*O[128-s]) sin
// smem: Ep/Em/Op/Om [64][32] floats + sbase[32][4] + sx[32][257]
#define SMEM1 (4*64*32*4 + 32*4*4 + 32*257*4)
__global__ __launch_bounds__(256, 3) void sc_k1(const float* __restrict__ x) {
    extern __shared__ float sm[];
    float* sEp = sm;                    // [s][row] 64*32
    float* sEm = sEp + 64 * 32;
    float* sOp = sEm + 64 * 32;
    float* sOm = sOp + 64 * 32;
    float* sbase = sOm + 64 * 32;       // [row][4]: x0, x128, E64, O64
    float* sx = sbase + 128;            // [row][257]
    int tid = threadIdx.x, bid = blockIdx.x;

    const float* gx = x + (size_t)bid * 8192;
    for (int q = tid; q < 8192; q += 256) {
        int r = q >> 8, c = q & 255;
        sx[r * 257 + c] = gx[q];
    }
    __syncthreads();
    for (int e = tid; e < 63 * 32; e += 256) {
        int row = e & 31, s = (e >> 5) + 1;        // 1..63
        float a = sx[row * 257 + s];
        float b = sx[row * 257 + 256 - s];
        float c = sx[row * 257 + 128 - s];
        float d = sx[row * 257 + 128 + s];
        float Es = a + b, Os = a - b;              // E[s], O[s]
        float Er = c + d, Or = c - d;              // E[128-s], O[128-s]
        sEp[s * 32 + row] = Es + Er;
        sEm[s * 32 + row] = Es - Er;
        sOm[s * 32 + row] = Os - Or;
        sOp[s * 32 + row] = Os + Or;
    }
    if (tid < 32) {
        int row = tid;
        sbase[row * 4 + 0] = sx[row * 257 + 0];
        sbase[row * 4 + 1] = sx[row * 257 + 128];
        sbase[row * 4 + 2] = sx[row * 257 + 64] + sx[row * 257 + 192];
        sbase[row * 4 + 3] = sx[row * 257 + 64] - sx[row * 257 + 192];
    }
    __syncthreads();

    int ky = tid & 31, r0 = (tid >> 5) * 4;
    int odd = ky & 1;
    float sgn = odd ? -1.f : 1.f;
    int m4 = ky & 3;
    float c64 = (m4 == 0) ? 1.f : (m4 == 2 ? -1.f : 0.f);
    float s64 = (m4 == 1) ? 1.f : (m4 == 3 ? -1.f : 0.f);
    const float* EE = odd ? sEm : sEp;
    const float* OO = odd ? sOp : sOm;

    float re[4], im[4];
#pragma unroll
    for (int r = 0; r < 4; r++) {
        const float* bp = sbase + (r0 + r) * 4;
        re[r] = bp[0] + sgn * bp[1] + c64 * bp[2];
        im[r] = -s64 * bp[3];
    }
#pragma unroll 7
    for (int s = 1; s < 64; s++) {
        float2 t = __ldg(&g_tw1[(s - 1) * 32 + ky]);       // coalesced, L1-resident
        float4 e4 = *(const float4*)(EE + s * 32 + r0);    // near-broadcast
        float4 o4 = *(const float4*)(OO + s * 32 + r0);
        re[0] += e4.x * t.x;  im[0] -= o4.x * t.y;
        re[1] += e4.y * t.x;  im[1] -= o4.y * t.y;
        re[2] += e4.z * t.x;  im[2] -= o4.z * t.y;
        re[3] += e4.w * t.x;  im[3] -= o4.w * t.y;
    }
    const float SC = 1.f / 256.f;
#pragma unroll
    for (int r = 0; r < 4; r++)
        g_X1[(size_t)(bid * 32 + r0 + r) * 32 + ky] = make_float2(re[r] * SC, im[r] * SC);
}

// ---------------- K2: DFT along x (256 -> 63), 4 freqs per thread ----------------
#define SMEM2 (264*8 + 8192*8)
__global__ void sc_k2() {
    extern __shared__ float sm[];
    float2* stab = (float2*)sm;            // 264
    float2* sX1  = stab + 264;             // [x][ky] : 8192
    int tid = threadIdx.x, bid = blockIdx.x;

    for (int q = tid; q < 264; q += 256) stab[q] = g_tab[q];
    {
        const float4* src = (const float4*)(g_X1 + (size_t)bid * 8192);
        float4* dst = (float4*)sX1;
        for (int q = tid; q < 4096; q += 256) dst[q] = src[q];
    }
    __syncthreads();

    int ky = tid & 31, g = tid >> 5;
    int b = bid >> 6, i = bid & 63;
    int bi = b * 64 + i;
    int f0 = g, f1 = g + 8, f2 = g + 16, f3 = g + 24;
    float Ac0=0,As0=0,Bc0=0,Bs0=0, Ac1=0,As1=0,Bc1=0,Bs1=0;
    float Ac2=0,As2=0,Bc2=0,Bs2=0, Ac3=0,As3=0,Bc3=0,Bs3=0;
    int p0 = 0, p1 = 0, p2 = 0, p3 = 0;
#pragma unroll 4
    for (int xx = 0; xx < 256; xx++) {
        float2 v = sX1[xx * 32 + ky];
        float2 t;
        t = stab[tp(p0)]; Ac0 += v.x*t.x; As0 += v.x*t.y; Bc0 += v.y*t.x; Bs0 += v.y*t.y; p0 = (p0 + f0) & 255;
        t = stab[tp(p1)]; Ac1 += v.x*t.x; As1 += v.x*t.y; Bc1 += v.y*t.x; Bs1 += v.y*t.y; p1 = (p1 + f1) & 255;
        t = stab[tp(p2)]; Ac2 += v.x*t.x; As2 += v.x*t.y; Bc2 += v.y*t.x; Bs2 += v.y*t.y; p2 = (p2 + f2) & 255;
        t = stab[tp(p3)]; Ac3 += v.x*t.x; As3 += v.x*t.y; Bc3 += v.y*t.x; Bs3 += v.y*t.y; p3 = (p3 + f3) & 255;
    }
#define K2OUT(FQ, AC, AS, BC, BS)                                                        \
    g_X2[(size_t)((31 + (FQ)) * 32 + ky) * 1024 + bi] = make_float2((AC)+(BS), (BC)-(AS)); \
    if ((FQ) > 0)                                                                        \
        g_X2[(size_t)((31 - (FQ)) * 32 + ky) * 1024 + bi] = make_float2((AC)-(BS), (BC)+(AS));
    K2OUT(f0, Ac0, As0, Bc0, Bs0)
    K2OUT(f1, Ac1, As1, Bc1, Bs1)
    K2OUT(f2, Ac2, As2, Bc2, Bs2)
    K2OUT(f3, Ac3, As3, Bc3, Bs3)
#undef K2OUT
}

// ---------------- K3: channel mix, block per (f,ky) ----------------
__global__ void sc_k3() {
    __shared__ __align__(16) float2 sW[4096];     // [i][o]
    __shared__ __align__(16) float2 sX[1024];     // [b][i]
    int tid = threadIdx.x, bid = blockIdx.x;      // bid = f*32+ky
    {
        const float4* srcW = (const float4*)(g_W + (size_t)bid * 4096);
        float4* dW = (float4*)sW;
        for (int q = tid; q < 2048; q += 256) dW[q] = srcW[q];
        const float4* srcX = (const float4*)(g_X2 + (size_t)bid * 1024);
        float4* dX = (float4*)sX;
        for (int q = tid; q < 512; q += 256) dX[q] = srcX[q];
    }
    __syncthreads();

    int o4 = (tid & 15) * 4, b = tid >> 4;
    float ar0 = 0, ai0 = 0, ar1 = 0, ai1 = 0, ar2 = 0, ai2 = 0, ar3 = 0, ai3 = 0;
#pragma unroll 4
    for (int i = 0; i < 64; i++) {
        float2 v = sX[b * 64 + i];
        const float4* wp = (const float4*)(sW + i * 64 + o4);
        float4 w01 = wp[0], w23 = wp[1];
        ar0 += v.x * w01.x - v.y * w01.y;  ai0 += v.x * w01.y + v.y * w01.x;
        ar1 += v.x * w01.z - v.y * w01.w;  ai1 += v.x * w01.w + v.y * w01.z;
        ar2 += v.x * w23.x - v.y * w23.y;  ai2 += v.x * w23.y + v.y * w23.x;
        ar3 += v.x * w23.z - v.y * w23.w;  ai3 += v.x * w23.w + v.y * w23.z;
    }
    size_t base = (size_t)(b * 64 + o4) * 2016 + bid;
    g_X3[base]          = make_float2(ar0, ai0);
    g_X3[base + 2016]   = make_float2(ar1, ai1);
    g_X3[base + 2*2016] = make_float2(ar2, ai2);
    g_X3[base + 3*2016] = make_float2(ar3, ai3);
}

// ---------------- K4: inverse DFT along x (63 -> 256), x-mirror fold ----------------
// Y[xx] = m + C + S ; Y[256-xx] = m + C - S ;  C = sum cos*U, S = sum sin*V
__global__ __launch_bounds__(256, 4) void sc_k4() {
    __shared__ __align__(16) float2 sX3[2016];
    __shared__ __align__(16) float2 sU[992], sV[992];   // [fq-1][ky]
    __shared__ __align__(16) float2 stab[264];
    int tid = threadIdx.x, bid = blockIdx.x;            // bid = b*64+o
    {
        const float4* src = (const float4*)(g_X3 + (size_t)bid * 2016);
        float4* dst = (float4*)sX3;
        for (int q = tid; q < 1008; q += 256) dst[q] = src[q];
        for (int q = tid; q < 264; q += 256) stab[q] = g_tab[q];
    }
    __syncthreads();
    for (int e = tid; e < 992; e += 256) {
        int ky = e & 31, fq = (e >> 5) + 1;
        float2 P = sX3[(31 + fq) * 32 + ky];
        float2 Q = sX3[(31 - fq) * 32 + ky];
        sU[e] = make_float2(P.x + Q.x, P.y + Q.y);
        sV[e] = make_float2(-(P.y - Q.y), P.x - Q.x);   // i*(P-Q)
    }
    __syncthreads();

    int ky4 = (tid & 7) * 4, xs = tid >> 3;
    const float4* m = (const float4*)(sX3 + 31 * 32 + ky4);
    float4 m01 = m[0], m23 = m[1];
    for (int xi = 0; xi < 4; xi++) {
        int xx = xs + 32 * xi;                          // 0..127
        float c0 = m01.x, c1 = m01.y, c2 = m01.z, c3 = m01.w;
        float c4 = m23.x, c5 = m23.y, c6 = m23.z, c7 = m23.w;
        float s0 = 0, s1 = 0, s2 = 0, s3 = 0, s4 = 0, s5 = 0, s6 = 0, s7 = 0;
        int p = 0;
#pragma unroll 4
        for (int fq = 1; fq < 32; fq++) {
            p = (p + xx) & 255;
            float2 t = stab[tp(p)];
            const float4* up = (const float4*)(sU + (fq - 1) * 32 + ky4);
            const float4* vp = (const float4*)(sV + (fq - 1) * 32 + ky4);
            float4 u01 = up[0], u23 = up[1], v01 = vp[0], v23 = vp[1];
            c0 += t.x * u01.x;  s0 += t.y * v01.x;
            c1 += t.x * u01.y;  s1 += t.y * v01.y;
            c2 += t.x * u01.z;  s2 += t.y * v01.z;
            c3 += t.x * u01.w;  s3 += t.y * v01.w;
            c4 += t.x * u23.x;  s4 += t.y * v23.x;
            c5 += t.x * u23.y;  s5 += t.y * v23.y;
            c6 += t.x * u23.z;  s6 += t.y * v23.z;
            c7 += t.x * u23.w;  s7 += t.y * v23.w;
        }
        float4* o1 = (float4*)(g_Y1 + (size_t)bid * 8192 + xx * 32 + ky4);
        o1[0] = make_float4(c0 + s0, c1 + s1, c2 + s2, c3 + s3);
        o1[1] = make_float4(c4 + s4, c5 + s5, c6 + s6, c7 + s7);
        if (xx > 0) {
            float4* o2 = (float4*)(g_Y1 + (size_t)bid * 8192 + (256 - xx) * 32 + ky4);
            o2[0] = make_float4(c0 - s0, c1 - s1, c2 - s2, c3 - s3);
            o2[1] = make_float4(c4 - s4, c5 - s5, c6 - s6, c7 - s7);
        }
    }
    // tail xx = 128 : cos = (-1)^fq, sin = 0
    if (tid < 32) {
        int ky = tid;
        float2 acc = sX3[31 * 32 + ky];
#pragma unroll 4
        for (int fq = 1; fq < 32; fq++) {
            float2 u = sU[(fq - 1) * 32 + ky];
            float sg = (fq & 1) ? -1.f : 1.f;
            acc.x += sg * u.x;  acc.y += sg * u.y;
        }
        g_Y1[(size_t)bid * 8192 + 128 * 32 + ky] = acc;
    }
}

// ---------------- K5: irfft along y, ky-parity fold (4 outputs per MAC set) ----------
__global__ __launch_bounds__(256, 4) void sc_k5(float* __restrict__ out) {
    __shared__ __align__(16) float2 sY[1024];       // [row(32)][ky(32)]
    __shared__ __align__(16) float2 stw[32*64];     // [ky][s] scaled, s=0..63
    int tid = threadIdx.x, bid = blockIdx.x;        // 32 rows per block, grid 8192
    {
        const float4* src = (const float4*)(g_Y1 + (size_t)bid * 1024);
        float4* dst = (float4*)sY;
        dst[tid]       = src[tid];
        dst[tid + 256] = src[tid + 256];
    }
    {
        const float4* src = (const float4*)g_tw5;
        float4* dst = (float4*)stw;
        for (int q = tid; q < 1024; q += 256) dst[q] = src[q];
    }
    __syncthreads();

    int l = tid & 31, w = tid >> 5, r0 = 4 * w;
    float Ae0[4]={0,0,0,0}, Ao0[4]={0,0,0,0}, Se0[4]={0,0,0,0}, So0[4]={0,0,0,0};
    float Ae1[4]={0,0,0,0}, Ao1[4]={0,0,0,0}, Se1[4]={0,0,0,0}, So1[4]={0,0,0,0};
#pragma unroll 4
    for (int k2 = 0; k2 < 16; k2++) {
        int kye = 2 * k2;
        float2 te0 = stw[kye * 64 + l];
        float2 te1 = stw[kye * 64 + l + 32];
        float2 to0 = stw[(kye + 1) * 64 + l];
        float2 to1 = stw[(kye + 1) * 64 + l + 32];
#pragma unroll
        for (int r = 0; r < 4; r++) {
            float4 v = *(const float4*)(sY + (r0 + r) * 32 + kye);  // (even ky, odd ky)
            Ae0[r] += v.x * te0.x;  Se0[r] += v.y * te0.y;
            Ae1[r] += v.x * te1.x;  Se1[r] += v.y * te1.y;
            Ao0[r] += v.z * to0.x;  So0[r] += v.w * to0.y;
            Ao1[r] += v.z * to1.x;  So1[r] += v.w * to1.y;
        }
    }
#pragma unroll
    for (int r = 0; r < 4; r++) {
        size_t ob = ((size_t)bid * 32 + r0 + r) * 256;
        float a  = Ae0[r] + Ao0[r], s  = Se0[r] + So0[r];
        float am = Ae0[r] - Ao0[r], sm = Se0[r] - So0[r];
        out[ob + l]       = a - s;                 // t = l
        out[ob + 128 - l] = am + sm;               // 128-t (t=0 -> out[128])
        if (l > 0) {
            out[ob + 256 - l] = a + s;
            out[ob + 128 + l] = am - sm;
        }
        float a1  = Ae1[r] + Ao1[r], s1  = Se1[r] + So1[r];
        float am1 = Ae1[r] - Ao1[r], sm1 = Se1[r] - So1[r];
        out[ob + 32 + l]  = a1 - s1;               // t = 32+l
        out[ob + 224 - l] = a1 + s1;               // 256-t
        out[ob + 96 - l]  = am1 + sm1;             // 128-t
        out[ob + 160 + l] = am1 - sm1;             // 128+t
    }
    // tail t = 64 / 192 : cos(pi*ky/2), sin(pi*ky/2) patterns; warp reduce over ky
    {
        int ky = l;
        float sc = (ky == 0) ? (1.f / 256.f) : (2.f / 256.f);
        int m4 = ky & 3;
        float c64 = (m4 == 0) ? sc : (m4 == 2 ? -sc : 0.f);
        float s64 = (m4 == 1) ? sc : (m4 == 3 ? -sc : 0.f);
#pragma unroll
        for (int r = 0; r < 4; r++) {
            float2 v = sY[(r0 + r) * 32 + ky];
            float p = v.x * c64 - v.y * s64;
            float q = v.x * c64 + v.y * s64;
#pragma unroll
            for (int off = 16; off; off >>= 1) {
                p += __shfl_xor_sync(0xFFFFFFFFu, p, off);
                q += __shfl_xor_sync(0xFFFFFFFFu, q, off);
            }
            if (l == 0) {
                size_t ob = ((size_t)bid * 32 + r0 + r) * 256;
                out[ob + 64]  = p;
                out[ob + 192] = q;
            }
        }
    }
}

// ---------------- launch ----------------
extern "C" void kernel_launch(void* const* d_in, const int* in_sizes, int n_in,
                              void* d_out, int out_size) {
    const float* x   = (const float*)d_in[0];
    const float* y0r = (const float*)d_in[1];
    const float* y0i = (const float*)d_in[2];
    const float* ypr = (const float*)d_in[3];
    const float* ypi = (const float*)d_in[4];
    const float* w00 = (const float*)d_in[5];
    float* out = (float*)d_out;

    cudaFuncSetAttribute(sc_k1, cudaFuncAttributeMaxDynamicSharedMemorySize, SMEM1);
    cudaFuncSetAttribute(sc_k2, cudaFuncAttributeMaxDynamicSharedMemorySize, SMEM2);

    sc_tabs<<<17, 256>>>();
    sc_build_w0<<<(63 * 4096 + 255) / 256, 256>>>(y0r, y0i, w00);
    sc_build_wt<<<dim3(62, 128), dim3(32, 8)>>>(ypr, ypi);
    sc_k1<<<8192, 256, SMEM1>>>(x);
    sc_k2<<<1024, 256, SMEM2>>>();
    sc_k3<<<2016, 256>>>();
    sc_k4<<<1024, 256>>>();
    sc_k5<<<8192, 256>>>(out);
}

// round 4
// speedup vs baseline: 2.1655x; 1.1478x over previous
#include <cuda_runtime.h>
#include <cstdint>

// Problem dims (fixed): B=16, Ci=Co=64, S=256, m1=m2=32
// ---------------- device scratch (no allocs allowed) ----------------
__device__ __align__(16) float2 g_tab[264];                       // padded cos/sin table (K4)
__device__ __align__(16) float2 g_tw1[63*32];                     // [s-1][ky] twiddles (K1, K2)
__device__ __align__(16) float2 g_tw5[32*64];                     // [ky][s] scaled twiddles for K5
__device__ __align__(16) float2 g_W [63*32*64*64];                // [f][ky][i][o]
__device__ __align__(16) float2 g_X1[16*64*256*32];               // [b][i][x][ky]
__device__ __align__(16) float2 g_X2[63*32*16*64];                // [f][ky][b][i]
__device__ __align__(16) float2 g_X3[16*64*63*32];                // [b][o][f][ky]
__device__ __align__(16) float2 g_Y1[16*64*256*32];               // [b][o][x][ky]

__device__ __forceinline__ int tp(int i) { return i + (i >> 5); }

// ---------------- init: all tables ----------------
__global__ void sc_tabs() {
    int t = blockIdx.x * 256 + threadIdx.x;
    if (t < 264) {
        int k = t / 33;
        int idx = t - k;
        float ang = (float)(6.283185307179586 * (double)idx / 256.0);
        g_tab[t] = make_float2(cosf(ang), sinf(ang));
    }
    int e1 = t - 264;
    if (e1 >= 0 && e1 < 63 * 32) {
        int s = (e1 >> 5) + 1, ky = e1 & 31;           // s = 1..63
        double ang = 6.283185307179586 * (double)((ky * s) % 256) / 256.0;
        g_tw1[e1] = make_float2((float)cos(ang), (float)sin(ang));
    }
    int e2 = t - 264 - 63 * 32;
    if (e2 >= 0 && e2 < 32 * 64) {
        int ky = e2 >> 6, s = e2 & 63;                 // s = 0..63
        double ang = 6.283185307179586 * (double)((s * ky) % 256) / 256.0;
        float sc = (ky == 0 ? 1.f : 2.f) / 256.f;
        g_tw5[e2] = make_float2(sc * (float)cos(ang), sc * (float)sin(ang));
    }
}

// ---------------- build W: ky=0 plane ----------------
__global__ void sc_build_w0(const float* __restrict__ y0r, const float* __restrict__ y0i,
                            const float* __restrict__ w00) {
    int t = blockIdx.x * 256 + threadIdx.x;
    if (t >= 63 * 4096) return;
    int io = t & 4095;
    int f  = t >> 12;
    float wr, wi;
    if (f < 31)       { wr = y0r[io * 31 + f];        wi = y0i[io * 31 + f]; }
    else if (f == 31) { wr = w00[io];                 wi = 0.f; }
    else              { wr = y0r[io * 31 + (62 - f)]; wi = -y0i[io * 31 + (62 - f)]; }
    g_W[(size_t)(f * 32) * 4096 + io] = make_float2(wr, wi);
}

// ---------------- build W: ky>=1 planes via tiled transpose ----------------
__global__ void sc_build_wt(const float* __restrict__ ypr, const float* __restrict__ ypi) {
    __shared__ float2 tile[32][33];
    int tx = threadIdx.x, ty = threadIdx.y;        // 32 x 8
    int fk0 = blockIdx.x * 32, io0 = blockIdx.y * 32;
#pragma unroll
    for (int k = 0; k < 4; k++) {
        int io = io0 + ty + 8 * k;
        int fk = fk0 + tx;
        if (fk < 1953)
            tile[ty + 8 * k][tx] = make_float2(ypr[(size_t)io * 1953 + fk],
                                               ypi[(size_t)io * 1953 + fk]);
    }
    __syncthreads();
#pragma unroll
    for (int k = 0; k < 4; k++) {
        int fk = fk0 + ty + 8 * k;
        if (fk < 1953) {
            int f  = fk / 31;
            int ky = fk - f * 31 + 1;
            g_W[(size_t)(f * 32 + ky) * 4096 + io0 + tx] = tile[tx][ty + 8 * k];
        }
    }
}

// ---------------- K1: DFT along y (256 real -> 32 complex), shfl fold, no sx ----------
// warp w owns rows 4w..4w+3; fold done in registers via butterfly shuffles.
__global__ __launch_bounds__(256, 4) void sc_k1(const float* __restrict__ x) {
    __shared__ float sEp[64 * 36], sEm[64 * 36], sOp[64 * 36], sOm[64 * 36];
    __shared__ float sbase[32 * 4];      // per row: x0, x128, x64+x192, x64-x192
    int tid = threadIdx.x, bid = blockIdx.x;
    int lane = tid & 31, w = tid >> 5;
    const float* gx = x + (size_t)bid * 8192;
    int sp = (32 - lane) & 31;

#pragma unroll
    for (int r = 0; r < 4; r++) {
        int row = 4 * w + r;
        const float* rp = gx + row * 256;
        float v[8];
#pragma unroll
        for (int k = 0; k < 8; k++) v[k] = rp[lane + 32 * k];
        // step 1: c <-> 256-c  (c = lane + 32k, k=0..3)
        float E1[4], O1[4];
#pragma unroll
        for (int k = 0; k < 4; k++) {
            float p1 = __shfl_sync(0xFFFFFFFFu, v[7 - k], sp);
            if (lane == 0) p1 = v[(8 - k) & 7];
            E1[k] = v[k] + p1;
            O1[k] = v[k] - p1;
        }
        // step 2: c <-> 128-c, c = lane + 32k, k=0,1
#pragma unroll
        for (int k = 0; k < 2; k++) {
            int c = lane + 32 * k;
            float qe = __shfl_sync(0xFFFFFFFFu, E1[3 - k], sp);
            float qo = __shfl_sync(0xFFFFFFFFu, O1[3 - k], sp);
            if (k == 1 && lane == 0) { qe = E1[3]; qo = O1[3]; }   // c=32 partner=96
            float ep = E1[k] + qe, em = E1[k] - qe;
            float op = O1[k] + qo, om = O1[k] - qo;
            if (c >= 1 && c <= 63) {
                sEp[c * 36 + row] = ep;
                sEm[c * 36 + row] = em;
                sOp[c * 36 + row] = op;
                sOm[c * 36 + row] = om;
            }
        }
        if (lane == 0) {
            sbase[row * 4 + 0] = v[0];
            sbase[row * 4 + 1] = v[4];
            sbase[row * 4 + 2] = v[2] + v[6];
            sbase[row * 4 + 3] = v[2] - v[6];
        }
    }
    __syncwarp();

    int ky = tid & 31, r0 = (tid >> 5) * 4;
    int odd = ky & 1;
    float sgn = odd ? -1.f : 1.f;
    int m4 = ky & 3;
    float c64 = (m4 == 0) ? 1.f : (m4 == 2 ? -1.f : 0.f);
    float s64 = (m4 == 1) ? 1.f : (m4 == 3 ? -1.f : 0.f);
    const float* EE = odd ? sEm : sEp;
    const float* OO = odd ? sOp : sOm;

    float re[4], im[4];
#pragma unroll
    for (int r = 0; r < 4; r++) {
        const float* bp = sbase + (r0 + r) * 4;
        re[r] = bp[0] + sgn * bp[1] + c64 * bp[2];
        im[r] = -s64 * bp[3];
    }
#pragma unroll 7
    for (int s = 1; s < 64; s++) {
        float2 t = __ldg(&g_tw1[(s - 1) * 32 + ky]);
        float4 e4 = *(const float4*)(EE + s * 36 + r0);
        float4 o4 = *(const float4*)(OO + s * 36 + r0);
        re[0] += e4.x * t.x;  im[0] -= o4.x * t.y;
        re[1] += e4.y * t.x;  im[1] -= o4.y * t.y;
        re[2] += e4.z * t.x;  im[2] -= o4.z * t.y;
        re[3] += e4.w * t.x;  im[3] -= o4.w * t.y;
    }
    const float SC = 1.f / 256.f;
#pragma unroll
    for (int r = 0; r < 4; r++)
        g_X1[(size_t)(bid * 32 + r0 + r) * 32 + ky] = make_float2(re[r] * SC, im[r] * SC);
}

// ---------------- K2: DFT along x (256 -> 63), 4x folded, in-place fold ----------------
// X2[f] = base + tail64 + sum_{x=1}^{63} EE_x cos - i OO_x sin  (parity-selected arrays)
#define SMEM2 (256*32*8)
__global__ __launch_bounds__(256, 3) void sc_k2() {
    extern __shared__ float sm2[];
    float2* sX1 = (float2*)sm2;            // [x][ky] : 256*32
    int tid = threadIdx.x, bid = blockIdx.x;
    {
        const float4* src = (const float4*)(g_X1 + (size_t)bid * 8192);
        float4* dst = (float4*)sX1;
        for (int q = tid; q < 4096; q += 256) dst[q] = src[q];
    }
    __syncthreads();

    // in-place fold: entry (x,ky) owns cells {x,256-x,128-x,128+x} x {ky}
    for (int e = tid; e < 63 * 32; e += 256) {
        int x = (e >> 5) + 1, ky = e & 31;
        float2 a = sX1[x * 32 + ky];
        float2 b = sX1[(256 - x) * 32 + ky];
        float2 c = sX1[(128 - x) * 32 + ky];
        float2 d = sX1[(128 + x) * 32 + ky];
        sX1[x * 32 + ky]         = make_float2(a.x + b.x + c.x + d.x, a.y + b.y + c.y + d.y); // Ep
        sX1[(256 - x) * 32 + ky] = make_float2(a.x + b.x - c.x - d.x, a.y + b.y - c.y - d.y); // Em
        sX1[(128 - x) * 32 + ky] = make_float2(a.x - b.x + c.x - d.x, a.y - b.y + c.y - d.y); // Op
        sX1[(128 + x) * 32 + ky] = make_float2(a.x - b.x - c.x + d.x, a.y - b.y - c.y + d.y); // Om
    }
    __syncthreads();

    int ky = tid & 31, g = tid >> 5;
    int b = bid >> 6, i = bid & 63;
    int bi = b * 64 + i;
    int p = g & 1;
    float Cr0=0,Ci0=0,Sr0=0,Si0=0, Cr1=0,Ci1=0,Sr1=0,Si1=0;
    float Cr2=0,Ci2=0,Sr2=0,Si2=0, Cr3=0,Ci3=0,Sr3=0,Si3=0;
#pragma unroll 7
    for (int x = 1; x < 64; x++) {
        int eeIdx = (p ? (256 - x) : x) * 32 + ky;
        int ooIdx = (p ? (128 - x) : (128 + x)) * 32 + ky;
        float2 e = sX1[eeIdx];
        float2 o = sX1[ooIdx];
        const float2* twr = &g_tw1[(x - 1) * 32];
        float2 t0 = __ldg(twr + g);
        float2 t1 = __ldg(twr + g + 8);
        float2 t2 = __ldg(twr + g + 16);
        float2 t3 = __ldg(twr + g + 24);
        Cr0 += e.x*t0.x; Ci0 += e.y*t0.x; Sr0 += o.x*t0.y; Si0 += o.y*t0.y;
        Cr1 += e.x*t1.x; Ci1 += e.y*t1.x; Sr1 += o.x*t1.y; Si1 += o.y*t1.y;
        Cr2 += e.x*t2.x; Ci2 += e.y*t2.x; Sr2 += o.x*t2.y; Si2 += o.y*t2.y;
        Cr3 += e.x*t3.x; Ci3 += e.y*t3.x; Sr3 += o.x*t3.y; Si3 += o.y*t3.y;
    }
    // base + tail (rows 0,64,128,192 untouched by fold)
    float2 b0   = sX1[0 * 32 + ky];
    float2 b128 = sX1[128 * 32 + ky];
    float2 x64  = sX1[64 * 32 + ky];
    float2 x192 = sX1[192 * 32 + ky];
    float sgnB = p ? -1.f : 1.f;
    float baseR = b0.x + sgnB * b128.x, baseI = b0.y + sgnB * b128.y;
    float E64r = x64.x + x192.x, E64i = x64.y + x192.y;
    float O64r = x64.x - x192.x, O64i = x64.y - x192.y;
    float tpR, tpI, tmR, tmI;
    int gm4 = g & 3;
    if (!p) {
        float c4 = (gm4 == 0) ? 1.f : -1.f;
        tpR = tmR = c4 * E64r;  tpI = tmI = c4 * E64i;
    } else {
        float s4 = (gm4 == 1) ? 1.f : -1.f;
        tpR = s4 * O64i;  tpI = -s4 * O64r;
        tmR = -s4 * O64i; tmI = s4 * O64r;
    }
#define K2OUT(FQ, CR, CI, SR, SI)                                                        \
    g_X2[(size_t)((31 + (FQ)) * 32 + ky) * 1024 + bi] =                                  \
        make_float2(baseR + tpR + (CR) + (SI), baseI + tpI + (CI) - (SR));               \
    if ((FQ) > 0)                                                                        \
        g_X2[(size_t)((31 - (FQ)) * 32 + ky) * 1024 + bi] =                              \
            make_float2(baseR + tmR + (CR) - (SI), baseI + tmI + (CI) + (SR));
    K2OUT(g,      Cr0, Ci0, Sr0, Si0)
    K2OUT(g + 8,  Cr1, Ci1, Sr1, Si1)
    K2OUT(g + 16, Cr2, Ci2, Sr2, Si2)
    K2OUT(g + 24, Cr3, Ci3, Sr3, Si3)
#undef K2OUT
}

// ---------------- K3: channel mix, 4 (f,ky) tiles/block, 4b x 4o register blocking ----
// W streamed from global (read exactly once); X tile in smem; staged coalesced output.
__global__ __launch_bounds__(256, 4) void sc_k3() {
    __shared__ __align__(16) float2 sX[4 * 1024];   // [tile][b*64+i]; reused as stage[bo*4+tile]
    int tid = threadIdx.x, bid = blockIdx.x;        // bid covers fk0 = bid*4
    int tile = tid >> 6, t = tid & 63;
    int og = t & 15, bg = t >> 4;                   // 16 o-groups x 4 b-groups
    int fk = bid * 4 + tile;
    {
        float4* dst = (float4*)sX;
        for (int q = tid; q < 2048; q += 256) {
            int tq = q >> 9;                        // 512 float4 per tile
            dst[q] = *(const float4*)(g_X2 + (size_t)(bid * 4 + tq) * 1024 + (q & 511) * 2);
        }
    }
    __syncthreads();

    float ar[4][4], ai[4][4];
#pragma unroll
    for (int bb = 0; bb < 4; bb++)
#pragma unroll
        for (int oo = 0; oo < 4; oo++) { ar[bb][oo] = 0.f; ai[bb][oo] = 0.f; }

    const float2* Wbase = g_W + (size_t)fk * 4096 + og * 4;
    const float2* Xbase = sX + tile * 1024 + bg * 4 * 64;
#pragma unroll 4
    for (int i = 0; i < 64; i++) {
        float4 w01 = __ldg((const float4*)(Wbase + i * 64));
        float4 w23 = __ldg((const float4*)(Wbase + i * 64 + 2));
        float2 v0 = Xbase[i];
        float2 v1 = Xbase[64 + i];
        float2 v2 = Xbase[128 + i];
        float2 v3 = Xbase[192 + i];
#define CMAC(BB, V)                                                          \
        ar[BB][0] += V.x*w01.x - V.y*w01.y;  ai[BB][0] += V.x*w01.y + V.y*w01.x; \
        ar[BB][1] += V.x*w01.z - V.y*w01.w;  ai[BB][1] += V.x*w01.w + V.y*w01.z; \
        ar[BB][2] += V.x*w23.x - V.y*w23.y;  ai[BB][2] += V.x*w23.y + V.y*w23.x; \
        ar[BB][3] += V.x*w23.z - V.y*w23.w;  ai[BB][3] += V.x*w23.w + V.y*w23.z;
        CMAC(0, v0) CMAC(1, v1) CMAC(2, v2) CMAC(3, v3)
#undef CMAC
    }
    __syncthreads();
    // stage results: stage[bo*4 + tile]
#pragma unroll
    for (int bb = 0; bb < 4; bb++)
#pragma unroll
        for (int oo = 0; oo < 4; oo++) {
            int bo = (bg * 4 + bb) * 64 + og * 4 + oo;
            sX[bo * 4 + tile] = make_float2(ar[bb][oo], ai[bb][oo]);
        }
    __syncthreads();
    int fk0 = bid * 4;
    for (int q = tid; q < 2048; q += 256) {
        int bo = q >> 1, half = q & 1;
        float4 val = *(const float4*)(sX + bo * 4 + half * 2);
        *(float4*)(g_X3 + (size_t)bo * 2016 + fk0 + half * 2) = val;
    }
}

// ---------------- K4: inverse DFT along x (63 -> 256), x-mirror fold ----------------
__global__ __launch_bounds__(256, 4) void sc_k4() {
    __shared__ __align__(16) float2 sX3[2016];
    __shared__ __align__(16) float2 sU[992], sV[992];   // [fq-1][ky]
    __shared__ __align__(16) float2 stab[264];
    int tid = threadIdx.x, bid = blockIdx.x;            // bid = b*64+o
    {
        const float4* src = (const float4*)(g_X3 + (size_t)bid * 2016);
        float4* dst = (float4*)sX3;
        for (int q = tid; q < 1008; q += 256) dst[q] = src[q];
        for (int q = tid; q < 264; q += 256) stab[q] = g_tab[q];
    }
    __syncthreads();
    for (int e = tid; e < 992; e += 256) {
        int ky = e & 31, fq = (e >> 5) + 1;
        float2 P = sX3[(31 + fq) * 32 + ky];
        float2 Q = sX3[(31 - fq) * 32 + ky];
        sU[e] = make_float2(P.x + Q.x, P.y + Q.y);
        sV[e] = make_float2(-(P.y - Q.y), P.x - Q.x);   // i*(P-Q)
    }
    __syncthreads();

    int ky4 = (tid & 7) * 4, xs = tid >> 3;
    const float4* m = (const float4*)(sX3 + 31 * 32 + ky4);
    float4 m01 = m[0], m23 = m[1];
    for (int xi = 0; xi < 4; xi++) {
        int xx = xs + 32 * xi;                          // 0..127
        float c0 = m01.x, c1 = m01.y, c2 = m01.z, c3 = m01.w;
        float c4 = m23.x, c5 = m23.y, c6 = m23.z, c7 = m23.w;
        float s0 = 0, s1 = 0, s2 = 0, s3 = 0, s4 = 0, s5 = 0, s6 = 0, s7 = 0;
        int p = 0;
#pragma unroll 4
        for (int fq = 1; fq < 32; fq++) {
            p = (p + xx) & 255;
            float2 t = stab[tp(p)];
            const float4* up = (const float4*)(sU + (fq - 1) * 32 + ky4);
            const float4* vp = (const float4*)(sV + (fq - 1) * 32 + ky4);
            float4 u01 = up[0], u23 = up[1], v01 = vp[0], v23 = vp[1];
            c0 += t.x * u01.x;  s0 += t.y * v01.x;
            c1 += t.x * u01.y;  s1 += t.y * v01.y;
            c2 += t.x * u01.z;  s2 += t.y * v01.z;
            c3 += t.x * u01.w;  s3 += t.y * v01.w;
            c4 += t.x * u23.x;  s4 += t.y * v23.x;
            c5 += t.x * u23.y;  s5 += t.y * v23.y;
            c6 += t.x * u23.z;  s6 += t.y * v23.z;
            c7 += t.x * u23.w;  s7 += t.y * v23.w;
        }
        float4* o1 = (float4*)(g_Y1 + (size_t)bid * 8192 + xx * 32 + ky4);
        o1[0] = make_float4(c0 + s0, c1 + s1, c2 + s2, c3 + s3);
        o1[1] = make_float4(c4 + s4, c5 + s5, c6 + s6, c7 + s7);
        if (xx > 0) {
            float4* o2 = (float4*)(g_Y1 + (size_t)bid * 8192 + (256 - xx) * 32 + ky4);
            o2[0] = make_float4(c0 - s0, c1 - s1, c2 - s2, c3 - s3);
            o2[1] = make_float4(c4 - s4, c5 - s5, c6 - s6, c7 - s7);
        }
    }
    // tail xx = 128 : cos = (-1)^fq, sin = 0
    if (tid < 32) {
        int ky = tid;
        float2 acc = sX3[31 * 32 + ky];
#pragma unroll 4
        for (int fq = 1; fq < 32; fq++) {
            float2 u = sU[(fq - 1) * 32 + ky];
            float sg = (fq & 1) ? -1.f : 1.f;
            acc.x += sg * u.x;  acc.y += sg * u.y;
        }
        g_Y1[(size_t)bid * 8192 + 128 * 32 + ky] = acc;
    }
}

// ---------------- K5: irfft along y, ky-parity fold (4 outputs per MAC set) ----------
__global__ __launch_bounds__(256, 4) void sc_k5(float* __restrict__ out) {
    __shared__ __align__(16) float2 sY[1024];       // [row(32)][ky(32)]
    __shared__ __align__(16) float2 stw[32*64];     // [ky][s] scaled, s=0..63
    int tid = threadIdx.x, bid = blockIdx.x;        // 32 rows per block, grid 8192
    {
        const float4* src = (const float4*)(g_Y1 + (size_t)bid * 1024);
        float4* dst = (float4*)sY;
        dst[tid]       = src[tid];
        dst[tid + 256] = src[tid + 256];
    }
    {
        const float4* src = (const float4*)g_tw5;
        float4* dst = (float4*)stw;
        for (int q = tid; q < 1024; q += 256) dst[q] = src[q];
    }
    __syncthreads();

    int l = tid & 31, w = tid >> 5, r0 = 4 * w;
    float Ae0[4]={0,0,0,0}, Ao0[4]={0,0,0,0}, Se0[4]={0,0,0,0}, So0[4]={0,0,0,0};
    float Ae1[4]={0,0,0,0}, Ao1[4]={0,0,0,0}, Se1[4]={0,0,0,0}, So1[4]={0,0,0,0};
#pragma unroll 4
    for (int k2 = 0; k2 < 16; k2++) {
        int kye = 2 * k2;
        float2 te0 = stw[kye * 64 + l];
        float2 te1 = stw[kye * 64 + l + 32];
        float2 to0 = stw[(kye + 1) * 64 + l];
        float2 to1 = stw[(kye + 1) * 64 + l + 32];
#pragma unroll
        for (int r = 0; r < 4; r++) {
            float4 v = *(const float4*)(sY + (r0 + r) * 32 + kye);  // (even ky, odd ky)
            Ae0[r] += v.x * te0.x;  Se0[r] += v.y * te0.y;
            Ae1[r] += v.x * te1.x;  Se1[r] += v.y * te1.y;
            Ao0[r] += v.z * to0.x;  So0[r] += v.w * to0.y;
            Ao1[r] += v.z * to1.x;  So1[r] += v.w * to1.y;
        }
    }
#pragma unroll
    for (int r = 0; r < 4; r++) {
        size_t ob = ((size_t)bid * 32 + r0 + r) * 256;
        float a  = Ae0[r] + Ao0[r], s  = Se0[r] + So0[r];
        float am = Ae0[r] - Ao0[r], sm = Se0[r] - So0[r];
        out[ob + l]       = a - s;                 // t = l
        out[ob + 128 - l] = am + sm;               // 128-t (t=0 -> out[128])
        if (l > 0) {
            out[ob + 256 - l] = a + s;
            out[ob + 128 + l] = am - sm;
        }
        float a1  = Ae1[r] + Ao1[r], s1  = Se1[r] + So1[r];
        float am1 = Ae1[r] - Ao1[r], sm1 = Se1[r] - So1[r];
        out[ob + 32 + l]  = a1 - s1;               // t = 32+l
        out[ob + 224 - l] = a1 + s1;               // 256-t
        out[ob + 96 - l]  = am1 + sm1;             // 128-t
        out[ob + 160 + l] = am1 - sm1;             // 128+t
    }
    // tail t = 64 / 192
    {
        int ky = l;
        float sc = (ky == 0) ? (1.f / 256.f) : (2.f / 256.f);
        int m4 = ky & 3;
        float c64 = (m4 == 0) ? sc : (m4 == 2 ? -sc : 0.f);
        float s64 = (m4 == 1) ? sc : (m4 == 3 ? -sc : 0.f);
#pragma unroll
        for (int r = 0; r < 4; r++) {
            float2 v = sY[(r0 + r) * 32 + ky];
            float p = v.x * c64 - v.y * s64;
            float q = v.x * c64 + v.y * s64;
#pragma unroll
            for (int off = 16; off; off >>= 1) {
                p += __shfl_xor_sync(0xFFFFFFFFu, p, off);
                q += __shfl_xor_sync(0xFFFFFFFFu, q, off);
            }
            if (l == 0) {
                size_t ob = ((size_t)bid * 32 + r0 + r) * 256;
                out[ob + 64]  = p;
                out[ob + 192] = q;
            }
        }
    }
}

// ---------------- launch ----------------
extern "C" void kernel_launch(void* const* d_in, const int* in_sizes, int n_in,
                              void* d_out, int out_size) {
    const float* x   = (const float*)d_in[0];
    const float* y0r = (const float*)d_in[1];
    const float* y0i = (const float*)d_in[2];
    const float* ypr = (const float*)d_in[3];
    const float* ypi = (const float*)d_in[4];
    const float* w00 = (const float*)d_in[5];
    float* out = (float*)d_out;

    cudaFuncSetAttribute(sc_k2, cudaFuncAttributeMaxDynamicSharedMemorySize, SMEM2);

    sc_tabs<<<17, 256>>>();
    sc_build_w0<<<(63 * 4096 + 255) / 256, 256>>>(y0r, y0i, w00);
    sc_build_wt<<<dim3(62, 128), dim3(32, 8)>>>(ypr, ypi);
    sc_k1<<<8192, 256>>>(x);
    sc_k2<<<1024, 256, SMEM2>>>();
    sc_k3<<<504, 256>>>();
    sc_k4<<<1024, 256>>>();
    sc_k5<<<8192, 256>>>(out);
}

// round 5
// speedup vs baseline: 2.3040x; 1.0640x over previous
#include <cuda_runtime.h>
#include <cstdint>

// Problem dims (fixed): B=16, Ci=Co=64, S=256, m1=m2=32
// ---------------- device scratch (no allocs allowed) ----------------
__device__ __align__(16) float2 g_tab[264];                       // padded cos/sin table (K4)
__device__ __align__(16) float2 g_tw1[63*32];                     // [s-1][ky] twiddles (K1 seed, K2)
__device__ __align__(16) float2 g_W [63*32*64*64];                // [f][ky][i][o]
__device__ __align__(16) float2 g_X1[16*64*256*32];               // [b][i][x][ky]
__device__ __align__(16) float2 g_X2[63*32*16*64];                // [f][ky][b][i]
__device__ __align__(16) float2 g_X3[16*64*63*32];                // [b][o][f][ky]
__device__ __align__(16) float2 g_Y1[16*64*256*32];               // [b][o][x][ky]

__device__ __forceinline__ int tp(int i) { return i + (i >> 5); }

// ---------------- init: all tables ----------------
__global__ void sc_tabs() {
    int t = blockIdx.x * 256 + threadIdx.x;
    if (t < 264) {
        int k = t / 33;
        int idx = t - k;
        float ang = (float)(6.283185307179586 * (double)idx / 256.0);
        g_tab[t] = make_float2(cosf(ang), sinf(ang));
    }
    int e1 = t - 264;
    if (e1 >= 0 && e1 < 63 * 32) {
        int s = (e1 >> 5) + 1, ky = e1 & 31;           // s = 1..63
        double ang = 6.283185307179586 * (double)((ky * s) % 256) / 256.0;
        g_tw1[e1] = make_float2((float)cos(ang), (float)sin(ang));
    }
}

// ---------------- build W: ky=0 plane ----------------
__global__ void sc_build_w0(const float* __restrict__ y0r, const float* __restrict__ y0i,
                            const float* __restrict__ w00) {
    int t = blockIdx.x * 256 + threadIdx.x;
    if (t >= 63 * 4096) return;
    int io = t & 4095;
    int f  = t >> 12;
    float wr, wi;
    if (f < 31)       { wr = y0r[io * 31 + f];        wi = y0i[io * 31 + f]; }
    else if (f == 31) { wr = w00[io];                 wi = 0.f; }
    else              { wr = y0r[io * 31 + (62 - f)]; wi = -y0i[io * 31 + (62 - f)]; }
    g_W[(size_t)(f * 32) * 4096 + io] = make_float2(wr, wi);
}

// ---------------- build W: ky>=1 planes via tiled transpose ----------------
__global__ void sc_build_wt(const float* __restrict__ ypr, const float* __restrict__ ypi) {
    __shared__ float2 tile[32][33];
    int tx = threadIdx.x, ty = threadIdx.y;        // 32 x 8
    int fk0 = blockIdx.x * 32, io0 = blockIdx.y * 32;
#pragma unroll
    for (int k = 0; k < 4; k++) {
        int io = io0 + ty + 8 * k;
        int fk = fk0 + tx;
        if (fk < 1953)
            tile[ty + 8 * k][tx] = make_float2(ypr[(size_t)io * 1953 + fk],
                                               ypi[(size_t)io * 1953 + fk]);
    }
    __syncthreads();
#pragma unroll
    for (int k = 0; k < 4; k++) {
        int fk = fk0 + ty + 8 * k;
        if (fk < 1953) {
            int f  = fk / 31;
            int ky = fk - f * 31 + 1;
            g_W[(size_t)(f * 32 + ky) * 4096 + io0 + tx] = tile[tx][ty + 8 * k];
        }
    }
}

// ---------------- K1: DFT along y, shfl fold + Chebyshev twiddle recurrence ----------
__global__ __launch_bounds__(256, 4) void sc_k1(const float* __restrict__ x) {
    __shared__ float sEp[64 * 36], sEm[64 * 36], sOp[64 * 36], sOm[64 * 36];
    __shared__ float sbase[32 * 4];      // per row: x0, x128, x64+x192, x64-x192
    int tid = threadIdx.x, bid = blockIdx.x;
    int lane = tid & 31, w = tid >> 5;
    const float* gx = x + (size_t)bid * 8192;
    int sp = (32 - lane) & 31;

#pragma unroll
    for (int r = 0; r < 4; r++) {
        int row = 4 * w + r;
        const float* rp = gx + row * 256;
        float v[8];
#pragma unroll
        for (int k = 0; k < 8; k++) v[k] = rp[lane + 32 * k];
        // step 1: c <-> 256-c
        float E1[4], O1[4];
#pragma unroll
        for (int k = 0; k < 4; k++) {
            float p1 = __shfl_sync(0xFFFFFFFFu, v[7 - k], sp);
            if (lane == 0) p1 = v[(8 - k) & 7];
            E1[k] = v[k] + p1;
            O1[k] = v[k] - p1;
        }
        // step 2: c <-> 128-c
#pragma unroll
        for (int k = 0; k < 2; k++) {
            int c = lane + 32 * k;
            float qe = __shfl_sync(0xFFFFFFFFu, E1[3 - k], sp);
            float qo = __shfl_sync(0xFFFFFFFFu, O1[3 - k], sp);
            if (k == 1 && lane == 0) { qe = E1[3]; qo = O1[3]; }
            float ep = E1[k] + qe, em = E1[k] - qe;
            float op = O1[k] + qo, om = O1[k] - qo;
            if (c >= 1 && c <= 63) {
                sEp[c * 36 + row] = ep;
                sEm[c * 36 + row] = em;
                sOp[c * 36 + row] = op;
                sOm[c * 36 + row] = om;
            }
        }
        if (lane == 0) {
            sbase[row * 4 + 0] = v[0];
            sbase[row * 4 + 1] = v[4];
            sbase[row * 4 + 2] = v[2] + v[6];
            sbase[row * 4 + 3] = v[2] - v[6];
        }
    }
    __syncwarp();

    int ky = tid & 31, r0 = (tid >> 5) * 4;
    int odd = ky & 1;
    float sgn = odd ? -1.f : 1.f;
    int m4 = ky & 3;
    float c64 = (m4 == 0) ? 1.f : (m4 == 2 ? -1.f : 0.f);
    float s64 = (m4 == 1) ? 1.f : (m4 == 3 ? -1.f : 0.f);
    const float* EE = odd ? sEm : sEp;
    const float* OO = odd ? sOp : sOm;

    float re[4], im[4];
#pragma unroll
    for (int r = 0; r < 4; r++) {
        const float* bp = sbase + (r0 + r) * 4;
        re[r] = bp[0] + sgn * bp[1] + c64 * bp[2];
        im[r] = -s64 * bp[3];
    }
    // Chebyshev chains for cos(s*theta), sin(s*theta), theta = 2*pi*ky/256
    float2 t1 = __ldg(&g_tw1[ky]);                  // s=1 seed (exact)
    float KK = 2.f * t1.x;
    float cp = 1.f, cc = t1.x;                      // cos(0), cos(theta)
    float zp = 0.f, zc = t1.y;                      // sin(0), sin(theta)
#pragma unroll 7
    for (int s = 1; s < 64; s++) {
        float4 e4 = *(const float4*)(EE + s * 36 + r0);
        float4 o4 = *(const float4*)(OO + s * 36 + r0);
        re[0] += e4.x * cc;  im[0] -= o4.x * zc;
        re[1] += e4.y * cc;  im[1] -= o4.y * zc;
        re[2] += e4.z * cc;  im[2] -= o4.z * zc;
        re[3] += e4.w * cc;  im[3] -= o4.w * zc;
        float cn = KK * cc - cp;  cp = cc;  cc = cn;
        float zn = KK * zc - zp;  zp = zc;  zc = zn;
    }
    const float SC = 1.f / 256.f;
#pragma unroll
    for (int r = 0; r < 4; r++)
        g_X1[(size_t)(bid * 32 + r0 + r) * 32 + ky] = make_float2(re[r] * SC, im[r] * SC);
}

// ---------------- K2: DFT along x (256 -> 63), 4x folded, in-place fold ----------------
#define SMEM2 (256*32*8)
__global__ __launch_bounds__(256, 3) void sc_k2() {
    extern __shared__ float sm2[];
    float2* sX1 = (float2*)sm2;            // [x][ky] : 256*32
    int tid = threadIdx.x, bid = blockIdx.x;
    {
        const float4* src = (const float4*)(g_X1 + (size_t)bid * 8192);
        float4* dst = (float4*)sX1;
        for (int q = tid; q < 4096; q += 256) dst[q] = src[q];
    }
    __syncthreads();

    for (int e = tid; e < 63 * 32; e += 256) {
        int x = (e >> 5) + 1, ky = e & 31;
        float2 a = sX1[x * 32 + ky];
        float2 b = sX1[(256 - x) * 32 + ky];
        float2 c = sX1[(128 - x) * 32 + ky];
        float2 d = sX1[(128 + x) * 32 + ky];
        sX1[x * 32 + ky]         = make_float2(a.x + b.x + c.x + d.x, a.y + b.y + c.y + d.y); // Ep
        sX1[(256 - x) * 32 + ky] = make_float2(a.x + b.x - c.x - d.x, a.y + b.y - c.y - d.y); // Em
        sX1[(128 - x) * 32 + ky] = make_float2(a.x - b.x + c.x - d.x, a.y - b.y + c.y - d.y); // Op
        sX1[(128 + x) * 32 + ky] = make_float2(a.x - b.x - c.x + d.x, a.y - b.y - c.y + d.y); // Om
    }
    __syncthreads();

    int ky = tid & 31, g = tid >> 5;
    int b = bid >> 6, i = bid & 63;
    int bi = b * 64 + i;
    int p = g & 1;
    float Cr0=0,Ci0=0,Sr0=0,Si0=0, Cr1=0,Ci1=0,Sr1=0,Si1=0;
    float Cr2=0,Ci2=0,Sr2=0,Si2=0, Cr3=0,Ci3=0,Sr3=0,Si3=0;
#pragma unroll 7
    for (int x = 1; x < 64; x++) {
        int eeIdx = (p ? (256 - x) : x) * 32 + ky;
        int ooIdx = (p ? (128 - x) : (128 + x)) * 32 + ky;
        float2 e = sX1[eeIdx];
        float2 o = sX1[ooIdx];
        const float2* twr = &g_tw1[(x - 1) * 32];
        float2 t0 = __ldg(twr + g);
        float2 t1 = __ldg(twr + g + 8);
        float2 t2 = __ldg(twr + g + 16);
        float2 t3 = __ldg(twr + g + 24);
        Cr0 += e.x*t0.x; Ci0 += e.y*t0.x; Sr0 += o.x*t0.y; Si0 += o.y*t0.y;
        Cr1 += e.x*t1.x; Ci1 += e.y*t1.x; Sr1 += o.x*t1.y; Si1 += o.y*t1.y;
        Cr2 += e.x*t2.x; Ci2 += e.y*t2.x; Sr2 += o.x*t2.y; Si2 += o.y*t2.y;
        Cr3 += e.x*t3.x; Ci3 += e.y*t3.x; Sr3 += o.x*t3.y; Si3 += o.y*t3.y;
    }
    float2 b0   = sX1[0 * 32 + ky];
    float2 b128 = sX1[128 * 32 + ky];
    float2 x64  = sX1[64 * 32 + ky];
    float2 x192 = sX1[192 * 32 + ky];
    float sgnB = p ? -1.f : 1.f;
    float baseR = b0.x + sgnB * b128.x, baseI = b0.y + sgnB * b128.y;
    float E64r = x64.x + x192.x, E64i = x64.y + x192.y;
    float O64r = x64.x - x192.x, O64i = x64.y - x192.y;
    float tpR, tpI, tmR, tmI;
    int gm4 = g & 3;
    if (!p) {
        float c4 = (gm4 == 0) ? 1.f : -1.f;
        tpR = tmR = c4 * E64r;  tpI = tmI = c4 * E64i;
    } else {
        float s4 = (gm4 == 1) ? 1.f : -1.f;
        tpR = s4 * O64i;  tpI = -s4 * O64r;
        tmR = -s4 * O64i; tmI = s4 * O64r;
    }
#define K2OUT(FQ, CR, CI, SR, SI)                                                        \
    g_X2[(size_t)((31 + (FQ)) * 32 + ky) * 1024 + bi] =                                  \
        make_float2(baseR + tpR + (CR) + (SI), baseI + tpI + (CI) - (SR));               \
    if ((FQ) > 0)                                                                        \
        g_X2[(size_t)((31 - (FQ)) * 32 + ky) * 1024 + bi] =                              \
            make_float2(baseR + tmR + (CR) - (SI), baseI + tmI + (CI) + (SR));
    K2OUT(g,      Cr0, Ci0, Sr0, Si0)
    K2OUT(g + 8,  Cr1, Ci1, Sr1, Si1)
    K2OUT(g + 16, Cr2, Ci2, Sr2, Si2)
    K2OUT(g + 24, Cr3, Ci3, Sr3, Si3)
#undef K2OUT
}

// ---------------- K3: channel mix, 4 (f,ky) tiles/block, 4b x 4o register blocking ----
__global__ __launch_bounds__(256, 4) void sc_k3() {
    __shared__ __align__(16) float2 sX[4 * 1024];   // [tile][b*64+i]; reused as stage[bo*4+tile]
    int tid = threadIdx.x, bid = blockIdx.x;        // bid covers fk0 = bid*4
    int tile = tid >> 6, t = tid & 63;
    int og = t & 15, bg = t >> 4;
    int fk = bid * 4 + tile;
    {
        float4* dst = (float4*)sX;
        for (int q = tid; q < 2048; q += 256) {
            int tq = q >> 9;
            dst[q] = *(const float4*)(g_X2 + (size_t)(bid * 4 + tq) * 1024 + (q & 511) * 2);
        }
    }
    __syncthreads();

    float ar[4][4], ai[4][4];
#pragma unroll
    for (int bb = 0; bb < 4; bb++)
#pragma unroll
        for (int oo = 0; oo < 4; oo++) { ar[bb][oo] = 0.f; ai[bb][oo] = 0.f; }

    const float2* Wbase = g_W + (size_t)fk * 4096 + og * 4;
    const float2* Xbase = sX + tile * 1024 + bg * 4 * 64;
#pragma unroll 4
    for (int i = 0; i < 64; i++) {
        float4 w01 = __ldg((const float4*)(Wbase + i * 64));
        float4 w23 = __ldg((const float4*)(Wbase + i * 64 + 2));
        float2 v0 = Xbase[i];
        float2 v1 = Xbase[64 + i];
        float2 v2 = Xbase[128 + i];
        float2 v3 = Xbase[192 + i];
#define CMAC(BB, V)                                                          \
        ar[BB][0] += V.x*w01.x - V.y*w01.y;  ai[BB][0] += V.x*w01.y + V.y*w01.x; \
        ar[BB][1] += V.x*w01.z - V.y*w01.w;  ai[BB][1] += V.x*w01.w + V.y*w01.z; \
        ar[BB][2] += V.x*w23.x - V.y*w23.y;  ai[BB][2] += V.x*w23.y + V.y*w23.x; \
        ar[BB][3] += V.x*w23.z - V.y*w23.w;  ai[BB][3] += V.x*w23.w + V.y*w23.z;
        CMAC(0, v0) CMAC(1, v1) CMAC(2, v2) CMAC(3, v3)
#undef CMAC
    }
    __syncthreads();
#pragma unroll
    for (int bb = 0; bb < 4; bb++)
#pragma unroll
        for (int oo = 0; oo < 4; oo++) {
            int bo = (bg * 4 + bb) * 64 + og * 4 + oo;
            sX[bo * 4 + tile] = make_float2(ar[bb][oo], ai[bb][oo]);
        }
    __syncthreads();
    int fk0 = bid * 4;
    for (int q = tid; q < 2048; q += 256) {
        int bo = q >> 1, half = q & 1;
        float4 val = *(const float4*)(sX + bo * 4 + half * 2);
        *(float4*)(g_X3 + (size_t)bo * 2016 + fk0 + half * 2) = val;
    }
}

// ---------------- K4: inverse DFT along x (63 -> 256), x-mirror fold ----------------
__global__ __launch_bounds__(256, 4) void sc_k4() {
    __shared__ __align__(16) float2 sX3[2016];
    __shared__ __align__(16) float2 sU[992], sV[992];   // [fq-1][ky]
    __shared__ __align__(16) float2 stab[264];
    int tid = threadIdx.x, bid = blockIdx.x;            // bid = b*64+o
    {
        const float4* src = (const float4*)(g_X3 + (size_t)bid * 2016);
        float4* dst = (float4*)sX3;
        for (int q = tid; q < 1008; q += 256) dst[q] = src[q];
        for (int q = tid; q < 264; q += 256) stab[q] = g_tab[q];
    }
    __syncthreads();
    for (int e = tid; e < 992; e += 256) {
        int ky = e & 31, fq = (e >> 5) + 1;
        float2 P = sX3[(31 + fq) * 32 + ky];
        float2 Q = sX3[(31 - fq) * 32 + ky];
        sU[e] = make_float2(P.x + Q.x, P.y + Q.y);
        sV[e] = make_float2(-(P.y - Q.y), P.x - Q.x);   // i*(P-Q)
    }
    __syncthreads();

    int ky4 = (tid & 7) * 4, xs = tid >> 3;
    const float4* m = (const float4*)(sX3 + 31 * 32 + ky4);
    float4 m01 = m[0], m23 = m[1];
    for (int xi = 0; xi < 4; xi++) {
        int xx = xs + 32 * xi;                          // 0..127
        float c0 = m01.x, c1 = m01.y, c2 = m01.z, c3 = m01.w;
        float c4 = m23.x, c5 = m23.y, c6 = m23.z, c7 = m23.w;
        float s0 = 0, s1 = 0, s2 = 0, s3 = 0, s4 = 0, s5 = 0, s6 = 0, s7 = 0;
        int p = 0;
#pragma unroll 4
        for (int fq = 1; fq < 32; fq++) {
            p = (p + xx) & 255;
            float2 t = stab[tp(p)];
            const float4* up = (const float4*)(sU + (fq - 1) * 32 + ky4);
            const float4* vp = (const float4*)(sV + (fq - 1) * 32 + ky4);
            float4 u01 = up[0], u23 = up[1], v01 = vp[0], v23 = vp[1];
            c0 += t.x * u01.x;  s0 += t.y * v01.x;
            c1 += t.x * u01.y;  s1 += t.y * v01.y;
            c2 += t.x * u01.z;  s2 += t.y * v01.z;
            c3 += t.x * u01.w;  s3 += t.y * v01.w;
            c4 += t.x * u23.x;  s4 += t.y * v23.x;
            c5 += t.x * u23.y;  s5 += t.y * v23.y;
            c6 += t.x * u23.z;  s6 += t.y * v23.z;
            c7 += t.x * u23.w;  s7 += t.y * v23.w;
        }
        float4* o1 = (float4*)(g_Y1 + (size_t)bid * 8192 + xx * 32 + ky4);
        o1[0] = make_float4(c0 + s0, c1 + s1, c2 + s2, c3 + s3);
        o1[1] = make_float4(c4 + s4, c5 + s5, c6 + s6, c7 + s7);
        if (xx > 0) {
            float4* o2 = (float4*)(g_Y1 + (size_t)bid * 8192 + (256 - xx) * 32 + ky4);
            o2[0] = make_float4(c0 - s0, c1 - s1, c2 - s2, c3 - s3);
            o2[1] = make_float4(c4 - s4, c5 - s5, c6 - s6, c7 - s7);
        }
    }
    if (tid < 32) {
        int ky = tid;
        float2 acc = sX3[31 * 32 + ky];
#pragma unroll 4
        for (int fq = 1; fq < 32; fq++) {
            float2 u = sU[(fq - 1) * 32 + ky];
            float sg = (fq & 1) ? -1.f : 1.f;
            acc.x += sg * u.x;  acc.y += sg * u.y;
        }
        g_Y1[(size_t)bid * 8192 + 128 * 32 + ky] = acc;
    }
}

// ---------------- K5: irfft along y, ky-parity fold + Chebyshev chains -------------
__global__ __launch_bounds__(256, 4) void sc_k5(float* __restrict__ out) {
    __shared__ __align__(16) float2 sY[1024];       // [row(32)][ky(32)]
    int tid = threadIdx.x, bid = blockIdx.x;        // 32 rows per block, grid 8192
    {
        const float4* src = (const float4*)(g_Y1 + (size_t)bid * 1024);
        float4* dst = (float4*)sY;
        dst[tid]       = src[tid];
        dst[tid + 256] = src[tid + 256];
    }
    __syncthreads();

    int l = tid & 31, w = tid >> 5, r0 = 4 * w;
    // Chebyshev chains in ky for s = l (A) and s = l+32 (B); angle thetaS = 2*pi*s/256
    float2 tA = __ldg(&g_tw1[l]);                   // (cos thetaA, sin thetaA), exact
    const float R45 = 0.70710678118654752f;
    float cB1 = (tA.x - tA.y) * R45;                // cos(thetaA + pi/4)
    float sB1 = (tA.x + tA.y) * R45;                // sin(thetaA + pi/4)
    float KA = 2.f * tA.x, KB = 2.f * cB1;
    // state: value at current ky (cur) and previous ky (prev); init ky=0 / ky=-1
    float cAc = 1.f, cAp = tA.x;
    float zAc = 0.f, zAp = -tA.y;
    float cBc = 1.f, cBp = cB1;
    float zBc = 0.f, zBp = -sB1;

    float Ae0[4]={0,0,0,0}, Se0[4]={0,0,0,0}, Ao0[4]={0,0,0,0}, So0[4]={0,0,0,0};
    float Ae1[4]={0,0,0,0}, Se1[4]={0,0,0,0}, Ao1[4]={0,0,0,0}, So1[4]={0,0,0,0};

#pragma unroll 4
    for (int kp = 0; kp < 16; kp++) {
        // advance chains to ky = 2kp+1 (odd)
        float n;
        n = KA * cAc - cAp;  cAp = cAc;  cAc = n;
        n = KA * zAc - zAp;  zAp = zAc;  zAc = n;
        n = KB * cBc - cBp;  cBp = cBc;  cBc = n;
        n = KB * zBc - zBp;  zBp = zBc;  zBc = n;
        int kyo = 2 * kp + 1;
#pragma unroll
        for (int r = 0; r < 4; r++) {
            float2 v = sY[(r0 + r) * 32 + kyo];
            Ao0[r] += v.x * cAc;  So0[r] += v.y * zAc;
            Ao1[r] += v.x * cBc;  So1[r] += v.y * zBc;
        }
        if (kp < 15) {
            // advance to ky = 2kp+2 (even)
            n = KA * cAc - cAp;  cAp = cAc;  cAc = n;
            n = KA * zAc - zAp;  zAp = zAc;  zAc = n;
            n = KB * cBc - cBp;  cBp = cBc;  cBc = n;
            n = KB * zBc - zBp;  zBp = zBc;  zBc = n;
            int kye = 2 * kp + 2;
#pragma unroll
            for (int r = 0; r < 4; r++) {
                float2 v = sY[(r0 + r) * 32 + kye];
                Ae0[r] += v.x * cAc;  Se0[r] += v.y * zAc;
                Ae1[r] += v.x * cBc;  Se1[r] += v.y * zBc;
            }
        }
    }

    const float SC1 = 1.f / 256.f, SC2 = 2.f / 256.f;
#pragma unroll
    for (int r = 0; r < 4; r++) {
        size_t ob = ((size_t)bid * 32 + r0 + r) * 256;
        float bx = sY[(r0 + r) * 32].x * SC1;        // ky=0 term (cos=1, sin=0)
        float a  = SC2 * (Ae0[r] + Ao0[r]) + bx;
        float s  = SC2 * (Se0[r] + So0[r]);
        float am = SC2 * (Ae0[r] - Ao0[r]) + bx;
        float sm = SC2 * (Se0[r] - So0[r]);
        out[ob + l]       = a - s;                 // t = l
        out[ob + 128 - l] = am + sm;               // 128-t
        if (l > 0) {
            out[ob + 256 - l] = a + s;
            out[ob + 128 + l] = am - sm;
        }
        float a1  = SC2 * (Ae1[r] + Ao1[r]) + bx;
        float s1  = SC2 * (Se1[r] + So1[r]);
        float am1 = SC2 * (Ae1[r] - Ao1[r]) + bx;
        float sm1 = SC2 * (Se1[r] - So1[r]);
        out[ob + 32 + l]  = a1 - s1;               // t = 32+l
        out[ob + 224 - l] = a1 + s1;               // 256-t
        out[ob + 96 - l]  = am1 + sm1;             // 128-t
        out[ob + 160 + l] = am1 - sm1;             // 128+t
    }
    // tail t = 64 / 192
    {
        int ky = l;
        float sc = (ky == 0) ? SC1 : SC2;
        int m4 = ky & 3;
        float c64 = (m4 == 0) ? sc : (m4 == 2 ? -sc : 0.f);
        float s64 = (m4 == 1) ? sc : (m4 == 3 ? -sc : 0.f);
#pragma unroll
        for (int r = 0; r < 4; r++) {
            float2 v = sY[(r0 + r) * 32 + ky];
            float p = v.x * c64 - v.y * s64;
            float q = v.x * c64 + v.y * s64;
#pragma unroll
            for (int off = 16; off; off >>= 1) {
                p += __shfl_xor_sync(0xFFFFFFFFu, p, off);
                q += __shfl_xor_sync(0xFFFFFFFFu, q, off);
            }
            if (l == 0) {
                size_t ob = ((size_t)bid * 32 + r0 + r) * 256;
                out[ob + 64]  = p;
                out[ob + 192] = q;
            }
        }
    }
}

// ---------------- launch ----------------
extern "C" void kernel_launch(void* const* d_in, const int* in_sizes, int n_in,
                              void* d_out, int out_size) {
    const float* x   = (const float*)d_in[0];
    const float* y0r = (const float*)d_in[1];
    const float* y0i = (const float*)d_in[2];
    const float* ypr = (const float*)d_in[3];
    const float* ypi = (const float*)d_in[4];
    const float* w00 = (const float*)d_in[5];
    float* out = (float*)d_out;

    cudaFuncSetAttribute(sc_k2, cudaFuncAttributeMaxDynamicSharedMemorySize, SMEM2);

    sc_tabs<<<9, 256>>>();
    sc_build_w0<<<(63 * 4096 + 255) / 256, 256>>>(y0r, y0i, w00);
    sc_build_wt<<<dim3(62, 128), dim3(32, 8)>>>(ypr, ypi);
    sc_k1<<<8192, 256>>>(x);
    sc_k2<<<1024, 256, SMEM2>>>();
    sc_k3<<<504, 256>>>();
    sc_k4<<<1024, 256>>>();
    sc_k5<<<8192, 256>>>(out);
}

// round 6
// speedup vs baseline: 2.5678x; 1.1145x over previous
#include <cuda_runtime.h>
#include <cstdint>

// Problem dims (fixed): B=16, Ci=Co=64, S=256, m1=m2=32
// ---------------- device scratch (no allocs allowed) ----------------
__device__ __align__(16) float2 g_tab[264];                       // padded cos/sin table (K4)
__device__ __align__(16) float2 g_tw1[63*32];                     // [s-1][ky] twiddles (K1 seed, K2)
__device__ __align__(16) float2 g_W [63*32*64*64];                // [f][ky][i][o]
__device__ __align__(16) float2 g_X1[16*64*256*32];               // [b][i][x][ky]
__device__ __align__(16) float2 g_X2[63*32*16*64];                // [f][ky][b][i]
__device__ __align__(16) float2 g_X3[16*64*63*32];                // [b][o][f][ky]
__device__ __align__(16) float2 g_Y1[16*64*256*32];               // [b][o][x][ky]

__device__ __forceinline__ int tp(int i) { return i + (i >> 5); }

// ---------------- init: all tables ----------------
__global__ void sc_tabs() {
    int t = blockIdx.x * 256 + threadIdx.x;
    if (t < 264) {
        int k = t / 33;
        int idx = t - k;
        float ang = (float)(6.283185307179586 * (double)idx / 256.0);
        g_tab[t] = make_float2(cosf(ang), sinf(ang));
    }
    int e1 = t - 264;
    if (e1 >= 0 && e1 < 63 * 32) {
        int s = (e1 >> 5) + 1, ky = e1 & 31;           // s = 1..63
        double ang = 6.283185307179586 * (double)((ky * s) % 256) / 256.0;
        g_tw1[e1] = make_float2((float)cos(ang), (float)sin(ang));
    }
}

// ---------------- build W: ky=0 plane ----------------
__global__ void sc_build_w0(const float* __restrict__ y0r, const float* __restrict__ y0i,
                            const float* __restrict__ w00) {
    int t = blockIdx.x * 256 + threadIdx.x;
    if (t >= 63 * 4096) return;
    int io = t & 4095;
    int f  = t >> 12;
    float wr, wi;
    if (f < 31)       { wr = y0r[io * 31 + f];        wi = y0i[io * 31 + f]; }
    else if (f == 31) { wr = w00[io];                 wi = 0.f; }
    else              { wr = y0r[io * 31 + (62 - f)]; wi = -y0i[io * 31 + (62 - f)]; }
    g_W[(size_t)(f * 32) * 4096 + io] = make_float2(wr, wi);
}

// ---------------- build W: ky>=1 planes via tiled transpose ----------------
__global__ void sc_build_wt(const float* __restrict__ ypr, const float* __restrict__ ypi) {
    __shared__ float2 tile[32][33];
    int tx = threadIdx.x, ty = threadIdx.y;        // 32 x 8
    int fk0 = blockIdx.x * 32, io0 = blockIdx.y * 32;
#pragma unroll
    for (int k = 0; k < 4; k++) {
        int io = io0 + ty + 8 * k;
        int fk = fk0 + tx;
        if (fk < 1953)
            tile[ty + 8 * k][tx] = make_float2(ypr[(size_t)io * 1953 + fk],
                                               ypi[(size_t)io * 1953 + fk]);
    }
    __syncthreads();
#pragma unroll
    for (int k = 0; k < 4; k++) {
        int fk = fk0 + ty + 8 * k;
        if (fk < 1953) {
            int f  = fk / 31;
            int ky = fk - f * 31 + 1;
            g_W[(size_t)(f * 32 + ky) * 4096 + io0 + tx] = tile[tx][ty + 8 * k];
        }
    }
}

// ---------------- K1: DFT along y, 4ky x 2row tiles, Chebyshev chains ----------------
// CTA = 64 rows, 256 threads. Warp w owns rows 8w..8w+7 (prologue + compute).
// Thread tile: ky in {ky0, ky0+8, ky0+16, ky0+24} (same parity), rows r0, r0+1.
#define SMEM1 ((4*64*66 + 64*4) * 4)
__global__ __launch_bounds__(256, 2) void sc_k1(const float* __restrict__ x) {
    extern __shared__ float sm1[];
    float* sEp = sm1;                    // [s][row] 64*66
    float* sEm = sEp + 64 * 66;
    float* sOp = sEm + 64 * 66;
    float* sOm = sOp + 64 * 66;
    float* sbase = sOm + 64 * 66;        // [row][4]: x0, x128, x64+x192, x64-x192
    int tid = threadIdx.x, bid = blockIdx.x;
    int lane = tid & 31, w = tid >> 5;
    const float* gx = x + (size_t)bid * 16384;      // 64 rows * 256
    int sp = (32 - lane) & 31;

#pragma unroll
    for (int r = 0; r < 8; r++) {
        int row = 8 * w + r;
        const float* rp = gx + row * 256;
        float v[8];
#pragma unroll
        for (int k = 0; k < 8; k++) v[k] = rp[lane + 32 * k];
        // step 1: c <-> 256-c
        float E1[4], O1[4];
#pragma unroll
        for (int k = 0; k < 4; k++) {
            float p1 = __shfl_sync(0xFFFFFFFFu, v[7 - k], sp);
            if (lane == 0) p1 = v[(8 - k) & 7];
            E1[k] = v[k] + p1;
            O1[k] = v[k] - p1;
        }
        // step 2: c <-> 128-c
#pragma unroll
        for (int k = 0; k < 2; k++) {
            int c = lane + 32 * k;
            float qe = __shfl_sync(0xFFFFFFFFu, E1[3 - k], sp);
            float qo = __shfl_sync(0xFFFFFFFFu, O1[3 - k], sp);
            if (k == 1 && lane == 0) { qe = E1[3]; qo = O1[3]; }
            float ep = E1[k] + qe, em = E1[k] - qe;
            float op = O1[k] + qo, om = O1[k] - qo;
            if (c >= 1 && c <= 63) {
                sEp[c * 66 + row] = ep;
                sEm[c * 66 + row] = em;
                sOp[c * 66 + row] = op;
                sOm[c * 66 + row] = om;
            }
        }
        if (lane == 0) {
            sbase[row * 4 + 0] = v[0];
            sbase[row * 4 + 1] = v[4];
            sbase[row * 4 + 2] = v[2] + v[6];
            sbase[row * 4 + 3] = v[2] - v[6];
        }
    }
    __syncwarp();

    int ky0 = lane & 7, rp2 = lane >> 3;
    int r0 = 8 * w + 2 * rp2;
    int p = ky0 & 1;
    float sgn = p ? -1.f : 1.f;
    int m4 = ky0 & 3;                    // (ky0+8j)&3 == ky0&3
    float c64 = (m4 == 0) ? 1.f : (m4 == 2 ? -1.f : 0.f);
    float s64 = (m4 == 1) ? 1.f : (m4 == 3 ? -1.f : 0.f);
    const float* EE = p ? sEm : sEp;
    const float* OO = p ? sOp : sOm;

    // 4 Chebyshev chains, ky_j = ky0 + 8j
    float K[4], cp[4], cc[4], zp[4], zc[4];
#pragma unroll
    for (int j = 0; j < 4; j++) {
        float2 t1 = __ldg(&g_tw1[ky0 + 8 * j]);     // s=1 seed (exact)
        K[j] = 2.f * t1.x;
        cp[j] = 1.f;  cc[j] = t1.x;
        zp[j] = 0.f;  zc[j] = t1.y;
    }
    float re[4][2], im[4][2];
    {
        const float* b0 = sbase + r0 * 4;
        const float* b1 = sbase + (r0 + 1) * 4;
        float base0 = b0[0] + sgn * b0[1] + c64 * b0[2];
        float base1 = b1[0] + sgn * b1[1] + c64 * b1[2];
        float imb0 = -s64 * b0[3];
        float imb1 = -s64 * b1[3];
#pragma unroll
        for (int j = 0; j < 4; j++) {
            re[j][0] = base0;  re[j][1] = base1;
            im[j][0] = imb0;   im[j][1] = imb1;
        }
    }
#pragma unroll 7
    for (int s = 1; s < 64; s++) {
        float2 e = *(const float2*)(EE + s * 66 + r0);
        float2 o = *(const float2*)(OO + s * 66 + r0);
#pragma unroll
        for (int j = 0; j < 4; j++) {
            re[j][0] += e.x * cc[j];  im[j][0] -= o.x * zc[j];
            re[j][1] += e.y * cc[j];  im[j][1] -= o.y * zc[j];
            float cn = K[j] * cc[j] - cp[j];  cp[j] = cc[j];  cc[j] = cn;
            float zn = K[j] * zc[j] - zp[j];  zp[j] = zc[j];  zc[j] = zn;
        }
    }
    const float SC = 1.f / 256.f;
#pragma unroll
    for (int j = 0; j < 4; j++) {
        int ky = ky0 + 8 * j;
#pragma unroll
        for (int r = 0; r < 2; r++)
            g_X1[(size_t)(bid * 64 + r0 + r) * 32 + ky] =
                make_float2(re[j][r] * SC, im[j][r] * SC);
    }
}

// ---------------- K2: DFT along x (256 -> 63), 4x folded, in-place fold ----------------
#define SMEM2 (256*32*8)
__global__ __launch_bounds__(256, 3) void sc_k2() {
    extern __shared__ float sm2[];
    float2* sX1 = (float2*)sm2;            // [x][ky] : 256*32
    int tid = threadIdx.x, bid = blockIdx.x;
    {
        const float4* src = (const float4*)(g_X1 + (size_t)bid * 8192);
        float4* dst = (float4*)sX1;
        for (int q = tid; q < 4096; q += 256) dst[q] = src[q];
    }
    __syncthreads();

    for (int e = tid; e < 63 * 32; e += 256) {
        int x = (e >> 5) + 1, ky = e & 31;
        float2 a = sX1[x * 32 + ky];
        float2 b = sX1[(256 - x) * 32 + ky];
        float2 c = sX1[(128 - x) * 32 + ky];
        float2 d = sX1[(128 + x) * 32 + ky];
        sX1[x * 32 + ky]         = make_float2(a.x + b.x + c.x + d.x, a.y + b.y + c.y + d.y); // Ep
        sX1[(256 - x) * 32 + ky] = make_float2(a.x + b.x - c.x - d.x, a.y + b.y - c.y - d.y); // Em
        sX1[(128 - x) * 32 + ky] = make_float2(a.x - b.x + c.x - d.x, a.y - b.y + c.y - d.y); // Op
        sX1[(128 + x) * 32 + ky] = make_float2(a.x - b.x - c.x + d.x, a.y - b.y - c.y + d.y); // Om
    }
    __syncthreads();

    int ky = tid & 31, g = tid >> 5;
    int b = bid >> 6, i = bid & 63;
    int bi = b * 64 + i;
    int p = g & 1;
    float Cr0=0,Ci0=0,Sr0=0,Si0=0, Cr1=0,Ci1=0,Sr1=0,Si1=0;
    float Cr2=0,Ci2=0,Sr2=0,Si2=0, Cr3=0,Ci3=0,Sr3=0,Si3=0;
#pragma unroll 7
    for (int x = 1; x < 64; x++) {
        int eeIdx = (p ? (256 - x) : x) * 32 + ky;
        int ooIdx = (p ? (128 - x) : (128 + x)) * 32 + ky;
        float2 e = sX1[eeIdx];
        float2 o = sX1[ooIdx];
        const float2* twr = &g_tw1[(x - 1) * 32];
        float2 t0 = __ldg(twr + g);
        float2 t1 = __ldg(twr + g + 8);
        float2 t2 = __ldg(twr + g + 16);
        float2 t3 = __ldg(twr + g + 24);
        Cr0 += e.x*t0.x; Ci0 += e.y*t0.x; Sr0 += o.x*t0.y; Si0 += o.y*t0.y;
        Cr1 += e.x*t1.x; Ci1 += e.y*t1.x; Sr1 += o.x*t1.y; Si1 += o.y*t1.y;
        Cr2 += e.x*t2.x; Ci2 += e.y*t2.x; Sr2 += o.x*t2.y; Si2 += o.y*t2.y;
        Cr3 += e.x*t3.x; Ci3 += e.y*t3.x; Sr3 += o.x*t3.y; Si3 += o.y*t3.y;
    }
    float2 b0   = sX1[0 * 32 + ky];
    float2 b128 = sX1[128 * 32 + ky];
    float2 x64  = sX1[64 * 32 + ky];
    float2 x192 = sX1[192 * 32 + ky];
    float sgnB = p ? -1.f : 1.f;
    float baseR = b0.x + sgnB * b128.x, baseI = b0.y + sgnB * b128.y;
    float E64r = x64.x + x192.x, E64i = x64.y + x192.y;
    float O64r = x64.x - x192.x, O64i = x64.y - x192.y;
    float tpR, tpI, tmR, tmI;
    int gm4 = g & 3;
    if (!p) {
        float c4 = (gm4 == 0) ? 1.f : -1.f;
        tpR = tmR = c4 * E64r;  tpI = tmI = c4 * E64i;
    } else {
        float s4 = (gm4 == 1) ? 1.f : -1.f;
        tpR = s4 * O64i;  tpI = -s4 * O64r;
        tmR = -s4 * O64i; tmI = s4 * O64r;
    }
#define K2OUT(FQ, CR, CI, SR, SI)                                                        \
    g_X2[(size_t)((31 + (FQ)) * 32 + ky) * 1024 + bi] =                                  \
        make_float2(baseR + tpR + (CR) + (SI), baseI + tpI + (CI) - (SR));               \
    if ((FQ) > 0)                                                                        \
        g_X2[(size_t)((31 - (FQ)) * 32 + ky) * 1024 + bi] =                              \
            make_float2(baseR + tmR + (CR) - (SI), baseI + tmI + (CI) + (SR));
    K2OUT(g,      Cr0, Ci0, Sr0, Si0)
    K2OUT(g + 8,  Cr1, Ci1, Sr1, Si1)
    K2OUT(g + 16, Cr2, Ci2, Sr2, Si2)
    K2OUT(g + 24, Cr3, Ci3, Sr3, Si3)
#undef K2OUT
}

// ---------------- K3: channel mix, 4 (f,ky) tiles/block, 4b x 4o register blocking ----
__global__ __launch_bounds__(256, 4) void sc_k3() {
    __shared__ __align__(16) float2 sX[4 * 1024];   // [tile][b*64+i]; reused as stage[bo*4+tile]
    int tid = threadIdx.x, bid = blockIdx.x;        // bid covers fk0 = bid*4
    int tile = tid >> 6, t = tid & 63;
    int og = t & 15, bg = t >> 4;
    int fk = bid * 4 + tile;
    {
        float4* dst = (float4*)sX;
        for (int q = tid; q < 2048; q += 256) {
            int tq = q >> 9;
            dst[q] = *(const float4*)(g_X2 + (size_t)(bid * 4 + tq) * 1024 + (q & 511) * 2);
        }
    }
    __syncthreads();

    float ar[4][4], ai[4][4];
#pragma unroll
    for (int bb = 0; bb < 4; bb++)
#pragma unroll
        for (int oo = 0; oo < 4; oo++) { ar[bb][oo] = 0.f; ai[bb][oo] = 0.f; }

    const float2* Wbase = g_W + (size_t)fk * 4096 + og * 4;
    const float2* Xbase = sX + tile * 1024 + bg * 4 * 64;
#pragma unroll 4
    for (int i = 0; i < 64; i++) {
        float4 w01 = __ldg((const float4*)(Wbase + i * 64));
        float4 w23 = __ldg((const float4*)(Wbase + i * 64 + 2));
        float2 v0 = Xbase[i];
        float2 v1 = Xbase[64 + i];
        float2 v2 = Xbase[128 + i];
        float2 v3 = Xbase[192 + i];
#define CMAC(BB, V)                                                          \
        ar[BB][0] += V.x*w01.x - V.y*w01.y;  ai[BB][0] += V.x*w01.y + V.y*w01.x; \
        ar[BB][1] += V.x*w01.z - V.y*w01.w;  ai[BB][1] += V.x*w01.w + V.y*w01.z; \
        ar[BB][2] += V.x*w23.x - V.y*w23.y;  ai[BB][2] += V.x*w23.y + V.y*w23.x; \
        ar[BB][3] += V.x*w23.z - V.y*w23.w;  ai[BB][3] += V.x*w23.w + V.y*w23.z;
        CMAC(0, v0) CMAC(1, v1) CMAC(2, v2) CMAC(3, v3)
#undef CMAC
    }
    __syncthreads();
#pragma unroll
    for (int bb = 0; bb < 4; bb++)
#pragma unroll
        for (int oo = 0; oo < 4; oo++) {
            int bo = (bg * 4 + bb) * 64 + og * 4 + oo;
            sX[bo * 4 + tile] = make_float2(ar[bb][oo], ai[bb][oo]);
        }
    __syncthreads();
    int fk0 = bid * 4;
    for (int q = tid; q < 2048; q += 256) {
        int bo = q >> 1, half = q & 1;
        float4 val = *(const float4*)(sX + bo * 4 + half * 2);
        *(float4*)(g_X3 + (size_t)bo * 2016 + fk0 + half * 2) = val;
    }
}

// ---------------- K4: inverse DFT along x (63 -> 256), x-mirror fold ----------------
__global__ __launch_bounds__(256, 4) void sc_k4() {
    __shared__ __align__(16) float2 sX3[2016];
    __shared__ __align__(16) float2 sU[992], sV[992];   // [fq-1][ky]
    __shared__ __align__(16) float2 stab[264];
    int tid = threadIdx.x, bid = blockIdx.x;            // bid = b*64+o
    {
        const float4* src = (const float4*)(g_X3 + (size_t)bid * 2016);
        float4* dst = (float4*)sX3;
        for (int q = tid; q < 1008; q += 256) dst[q] = src[q];
        for (int q = tid; q < 264; q += 256) stab[q] = g_tab[q];
    }
    __syncthreads();
    for (int e = tid; e < 992; e += 256) {
        int ky = e & 31, fq = (e >> 5) + 1;
        float2 P = sX3[(31 + fq) * 32 + ky];
        float2 Q = sX3[(31 - fq) * 32 + ky];
        sU[e] = make_float2(P.x + Q.x, P.y + Q.y);
        sV[e] = make_float2(-(P.y - Q.y), P.x - Q.x);   // i*(P-Q)
    }
    __syncthreads();

    int ky4 = (tid & 7) * 4, xs = tid >> 3;
    const float4* m = (const float4*)(sX3 + 31 * 32 + ky4);
    float4 m01 = m[0], m23 = m[1];
    for (int xi = 0; xi < 4; xi++) {
        int xx = xs + 32 * xi;                          // 0..127
        float c0 = m01.x, c1 = m01.y, c2 = m01.z, c3 = m01.w;
        float c4 = m23.x, c5 = m23.y, c6 = m23.z, c7 = m23.w;
        float s0 = 0, s1 = 0, s2 = 0, s3 = 0, s4 = 0, s5 = 0, s6 = 0, s7 = 0;
        int p = 0;
#pragma unroll 4
        for (int fq = 1; fq < 32; fq++) {
            p = (p + xx) & 255;
            float2 t = stab[tp(p)];
            const float4* up = (const float4*)(sU + (fq - 1) * 32 + ky4);
            const float4* vp = (const float4*)(sV + (fq - 1) * 32 + ky4);
            float4 u01 = up[0], u23 = up[1], v01 = vp[0], v23 = vp[1];
            c0 += t.x * u01.x;  s0 += t.y * v01.x;
            c1 += t.x * u01.y;  s1 += t.y * v01.y;
            c2 += t.x * u01.z;  s2 += t.y * v01.z;
            c3 += t.x * u01.w;  s3 += t.y * v01.w;
            c4 += t.x * u23.x;  s4 += t.y * v23.x;
            c5 += t.x * u23.y;  s5 += t.y * v23.y;
            c6 += t.x * u23.z;  s6 += t.y * v23.z;
            c7 += t.x * u23.w;  s7 += t.y * v23.w;
        }
        float4* o1 = (float4*)(g_Y1 + (size_t)bid * 8192 + xx * 32 + ky4);
        o1[0] = make_float4(c0 + s0, c1 + s1, c2 + s2, c3 + s3);
        o1[1] = make_float4(c4 + s4, c5 + s5, c6 + s6, c7 + s7);
        if (xx > 0) {
            float4* o2 = (float4*)(g_Y1 + (size_t)bid * 8192 + (256 - xx) * 32 + ky4);
            o2[0] = make_float4(c0 - s0, c1 - s1, c2 - s2, c3 - s3);
            o2[1] = make_float4(c4 - s4, c5 - s5, c6 - s6, c7 - s7);
        }
    }
    if (tid < 32) {
        int ky = tid;
        float2 acc = sX3[31 * 32 + ky];
#pragma unroll 4
        for (int fq = 1; fq < 32; fq++) {
            float2 u = sU[(fq - 1) * 32 + ky];
            float sg = (fq & 1) ? -1.f : 1.f;
            acc.x += sg * u.x;  acc.y += sg * u.y;
        }
        g_Y1[(size_t)bid * 8192 + 128 * 32 + ky] = acc;
    }
}

// ---------------- K5: irfft along y, ky-parity fold + Chebyshev chains -------------
__global__ __launch_bounds__(256, 4) void sc_k5(float* __restrict__ out) {
    __shared__ __align__(16) float2 sY[1024];       // [row(32)][ky(32)]
    int tid = threadIdx.x, bid = blockIdx.x;        // 32 rows per block, grid 8192
    {
        const float4* src = (const float4*)(g_Y1 + (size_t)bid * 1024);
        float4* dst = (float4*)sY;
        dst[tid]       = src[tid];
        dst[tid + 256] = src[tid + 256];
    }
    __syncthreads();

    int l = tid & 31, w = tid >> 5, r0 = 4 * w;
    float2 tA = __ldg(&g_tw1[l]);                   // (cos thetaA, sin thetaA), exact
    const float R45 = 0.70710678118654752f;
    float cB1 = (tA.x - tA.y) * R45;                // cos(thetaA + pi/4)
    float sB1 = (tA.x + tA.y) * R45;                // sin(thetaA + pi/4)
    float KA = 2.f * tA.x, KB = 2.f * cB1;
    float cAc = 1.f, cAp = tA.x;
    float zAc = 0.f, zAp = -tA.y;
    float cBc = 1.f, cBp = cB1;
    float zBc = 0.f, zBp = -sB1;

    float Ae0[4]={0,0,0,0}, Se0[4]={0,0,0,0}, Ao0[4]={0,0,0,0}, So0[4]={0,0,0,0};
    float Ae1[4]={0,0,0,0}, Se1[4]={0,0,0,0}, Ao1[4]={0,0,0,0}, So1[4]={0,0,0,0};

#pragma unroll 4
    for (int kp = 0; kp < 16; kp++) {
        float n;
        n = KA * cAc - cAp;  cAp = cAc;  cAc = n;
        n = KA * zAc - zAp;  zAp = zAc;  zAc = n;
        n = KB * cBc - cBp;  cBp = cBc;  cBc = n;
        n = KB * zBc - zBp;  zBp = zBc;  zBc = n;
        int kyo = 2 * kp + 1;
#pragma unroll
        for (int r = 0; r < 4; r++) {
            float2 v = sY[(r0 + r) * 32 + kyo];
            Ao0[r] += v.x * cAc;  So0[r] += v.y * zAc;
            Ao1[r] += v.x * cBc;  So1[r] += v.y * zBc;
        }
        if (kp < 15) {
            n = KA * cAc - cAp;  cAp = cAc;  cAc = n;
            n = KA * zAc - zAp;  zAp = zAc;  zAc = n;
            n = KB * cBc - cBp;  cBp = cBc;  cBc = n;
            n = KB * zBc - zBp;  zBp = zBc;  zBc = n;
            int kye = 2 * kp + 2;
#pragma unroll
            for (int r = 0; r < 4; r++) {
                float2 v = sY[(r0 + r) * 32 + kye];
                Ae0[r] += v.x * cAc;  Se0[r] += v.y * zAc;
                Ae1[r] += v.x * cBc;  Se1[r] += v.y * zBc;
            }
        }
    }

    const float SC1 = 1.f / 256.f, SC2 = 2.f / 256.f;
#pragma unroll
    for (int r = 0; r < 4; r++) {
        size_t ob = ((size_t)bid * 32 + r0 + r) * 256;
        float bx = sY[(r0 + r) * 32].x * SC1;
        float a  = SC2 * (Ae0[r] + Ao0[r]) + bx;
        float s  = SC2 * (Se0[r] + So0[r]);
        float am = SC2 * (Ae0[r] - Ao0[r]) + bx;
        float sm = SC2 * (Se0[r] - So0[r]);
        out[ob + l]       = a - s;
        out[ob + 128 - l] = am + sm;
        if (l > 0) {
            out[ob + 256 - l] = a + s;
            out[ob + 128 + l] = am - sm;
        }
        float a1  = SC2 * (Ae1[r] + Ao1[r]) + bx;
        float s1  = SC2 * (Se1[r] + So1[r]);
        float am1 = SC2 * (Ae1[r] - Ao1[r]) + bx;
        float sm1 = SC2 * (Se1[r] - So1[r]);
        out[ob + 32 + l]  = a1 - s1;
        out[ob + 224 - l] = a1 + s1;
        out[ob + 96 - l]  = am1 + sm1;
        out[ob + 160 + l] = am1 - sm1;
    }
    {
        int ky = l;
        float sc = (ky == 0) ? SC1 : SC2;
        int m4 = ky & 3;
        float c64 = (m4 == 0) ? sc : (m4 == 2 ? -sc : 0.f);
        float s64 = (m4 == 1) ? sc : (m4 == 3 ? -sc : 0.f);
#pragma unroll
        for (int r = 0; r < 4; r++) {
            float2 v = sY[(r0 + r) * 32 + ky];
            float p = v.x * c64 - v.y * s64;
            float q = v.x * c64 + v.y * s64;
#pragma unroll
            for (int off = 16; off; off >>= 1) {
                p += __shfl_xor_sync(0xFFFFFFFFu, p, off);
                q += __shfl_xor_sync(0xFFFFFFFFu, q, off);
            }
            if (l == 0) {
                size_t ob = ((size_t)bid * 32 + r0 + r) * 256;
                out[ob + 64]  = p;
                out[ob + 192] = q;
            }
        }
    }
}

// ---------------- launch ----------------
extern "C" void kernel_launch(void* const* d_in, const int* in_sizes, int n_in,
                              void* d_out, int out_size) {
    const float* x   = (const float*)d_in[0];
    const float* y0r = (const float*)d_in[1];
    const float* y0i = (const float*)d_in[2];
    const float* ypr = (const float*)d_in[3];
    const float* ypi = (const float*)d_in[4];
    const float* w00 = (const float*)d_in[5];
    float* out = (float*)d_out;

    cudaFuncSetAttribute(sc_k1, cudaFuncAttributeMaxDynamicSharedMemorySize, SMEM1);
    cudaFuncSetAttribute(sc_k2, cudaFuncAttributeMaxDynamicSharedMemorySize, SMEM2);

    sc_tabs<<<9, 256>>>();
    sc_build_w0<<<(63 * 4096 + 255) / 256, 256>>>(y0r, y0i, w00);
    sc_build_wt<<<dim3(62, 128), dim3(32, 8)>>>(ypr, ypi);
    sc_k1<<<4096, 256, SMEM1>>>(x);
    sc_k2<<<1024, 256, SMEM2>>>();
    sc_k3<<<504, 256>>>();
    sc_k4<<<1024, 256>>>();
    sc_k5<<<8192, 256>>>(out);
}

// round 7
// speedup vs baseline: 2.5696x; 1.0007x over previous
#include <cuda_runtime.h>
#include <cstdint>

// Problem dims (fixed): B=16, Ci=Co=64, S=256, m1=m2=32
// ---------------- device scratch (no allocs allowed) ----------------
__device__ __align__(16) float2 g_tab[264];                       // padded cos/sin table (K45)
__device__ __align__(16) float2 g_tw1[63*32];                     // [s-1][ky] twiddles (K1 seed, K2, K45)
__device__ __align__(16) float2 g_W [63*32*64*64];                // [f][ky][i][o]
__device__ __align__(16) float2 g_X1[16*64*256*32];               // [b][i][x][ky]
__device__ __align__(16) float2 g_X2[63*32*16*64];                // [f][ky][b][i]
__device__ __align__(16) float2 g_X3[16*64*63*32];                // [b][o][f][ky]

__device__ __forceinline__ int tp(int i) { return i + (i >> 5); }

// ---------------- init: all tables ----------------
__global__ void sc_tabs() {
    int t = blockIdx.x * 256 + threadIdx.x;
    if (t < 264) {
        int k = t / 33;
        int idx = t - k;
        float ang = (float)(6.283185307179586 * (double)idx / 256.0);
        g_tab[t] = make_float2(cosf(ang), sinf(ang));
    }
    int e1 = t - 264;
    if (e1 >= 0 && e1 < 63 * 32) {
        int s = (e1 >> 5) + 1, ky = e1 & 31;           // s = 1..63
        double ang = 6.283185307179586 * (double)((ky * s) % 256) / 256.0;
        g_tw1[e1] = make_float2((float)cos(ang), (float)sin(ang));
    }
}

// ---------------- build W: ky=0 plane ----------------
__global__ void sc_build_w0(const float* __restrict__ y0r, const float* __restrict__ y0i,
                            const float* __restrict__ w00) {
    int t = blockIdx.x * 256 + threadIdx.x;
    if (t >= 63 * 4096) return;
    int io = t & 4095;
    int f  = t >> 12;
    float wr, wi;
    if (f < 31)       { wr = y0r[io * 31 + f];        wi = y0i[io * 31 + f]; }
    else if (f == 31) { wr = w00[io];                 wi = 0.f; }
    else              { wr = y0r[io * 31 + (62 - f)]; wi = -y0i[io * 31 + (62 - f)]; }
    g_W[(size_t)(f * 32) * 4096 + io] = make_float2(wr, wi);
}

// ---------------- build W: ky>=1 planes via tiled transpose ----------------
__global__ void sc_build_wt(const float* __restrict__ ypr, const float* __restrict__ ypi) {
    __shared__ float2 tile[32][33];
    int tx = threadIdx.x, ty = threadIdx.y;        // 32 x 8
    int fk0 = blockIdx.x * 32, io0 = blockIdx.y * 32;
#pragma unroll
    for (int k = 0; k < 4; k++) {
        int io = io0 + ty + 8 * k;
        int fk = fk0 + tx;
        if (fk < 1953)
            tile[ty + 8 * k][tx] = make_float2(ypr[(size_t)io * 1953 + fk],
                                               ypi[(size_t)io * 1953 + fk]);
    }
    __syncthreads();
#pragma unroll
    for (int k = 0; k < 4; k++) {
        int fk = fk0 + ty + 8 * k;
        if (fk < 1953) {
            int f  = fk / 31;
            int ky = fk - f * 31 + 1;
            g_W[(size_t)(f * 32 + ky) * 4096 + io0 + tx] = tile[tx][ty + 8 * k];
        }
    }
}

// ---------------- K1: DFT along y, 4ky x 2row tiles, Chebyshev chains ----------------
#define SMEM1 ((4*64*66 + 64*4) * 4)
__global__ __launch_bounds__(256, 3) void sc_k1(const float* __restrict__ x) {
    extern __shared__ float sm1[];
    float* sEp = sm1;                    // [s][row] 64*66
    float* sEm = sEp + 64 * 66;
    float* sOp = sEm + 64 * 66;
    float* sOm = sOp + 64 * 66;
    float* sbase = sOm + 64 * 66;        // [row][4]
    int tid = threadIdx.x, bid = blockIdx.x;
    int lane = tid & 31, w = tid >> 5;
    const float* gx = x + (size_t)bid * 16384;      // 64 rows * 256
    int sp = (32 - lane) & 31;

#pragma unroll
    for (int r = 0; r < 8; r++) {
        int row = 8 * w + r;
        const float* rp = gx + row * 256;
        float v[8];
#pragma unroll
        for (int k = 0; k < 8; k++) v[k] = rp[lane + 32 * k];
        float E1[4], O1[4];
#pragma unroll
        for (int k = 0; k < 4; k++) {
            float p1 = __shfl_sync(0xFFFFFFFFu, v[7 - k], sp);
            if (lane == 0) p1 = v[(8 - k) & 7];
            E1[k] = v[k] + p1;
            O1[k] = v[k] - p1;
        }
#pragma unroll
        for (int k = 0; k < 2; k++) {
            int c = lane + 32 * k;
            float qe = __shfl_sync(0xFFFFFFFFu, E1[3 - k], sp);
            float qo = __shfl_sync(0xFFFFFFFFu, O1[3 - k], sp);
            if (k == 1 && lane == 0) { qe = E1[3]; qo = O1[3]; }
            float ep = E1[k] + qe, em = E1[k] - qe;
            float op = O1[k] + qo, om = O1[k] - qo;
            if (c >= 1 && c <= 63) {
                sEp[c * 66 + row] = ep;
                sEm[c * 66 + row] = em;
                sOp[c * 66 + row] = op;
                sOm[c * 66 + row] = om;
            }
        }
        if (lane == 0) {
            sbase[row * 4 + 0] = v[0];
            sbase[row * 4 + 1] = v[4];
            sbase[row * 4 + 2] = v[2] + v[6];
            sbase[row * 4 + 3] = v[2] - v[6];
        }
    }
    __syncwarp();

    int ky0 = lane & 7, rp2 = lane >> 3;
    int r0 = 8 * w + 2 * rp2;
    int p = ky0 & 1;
    float sgn = p ? -1.f : 1.f;
    int m4 = ky0 & 3;
    float c64 = (m4 == 0) ? 1.f : (m4 == 2 ? -1.f : 0.f);
    float s64 = (m4 == 1) ? 1.f : (m4 == 3 ? -1.f : 0.f);
    const float* EE = p ? sEm : sEp;
    const float* OO = p ? sOp : sOm;

    float K[4], cp[4], cc[4], zp[4], zc[4];
#pragma unroll
    for (int j = 0; j < 4; j++) {
        float2 t1 = __ldg(&g_tw1[ky0 + 8 * j]);
        K[j] = 2.f * t1.x;
        cp[j] = 1.f;  cc[j] = t1.x;
        zp[j] = 0.f;  zc[j] = t1.y;
    }
    float re[4][2], im[4][2];
    {
        const float* b0 = sbase + r0 * 4;
        const float* b1 = sbase + (r0 + 1) * 4;
        float base0 = b0[0] + sgn * b0[1] + c64 * b0[2];
        float base1 = b1[0] + sgn * b1[1] + c64 * b1[2];
        float imb0 = -s64 * b0[3];
        float imb1 = -s64 * b1[3];
#pragma unroll
        for (int j = 0; j < 4; j++) {
            re[j][0] = base0;  re[j][1] = base1;
            im[j][0] = imb0;   im[j][1] = imb1;
        }
    }
#pragma unroll 7
    for (int s = 1; s < 64; s++) {
        float2 e = *(const float2*)(EE + s * 66 + r0);
        float2 o = *(const float2*)(OO + s * 66 + r0);
#pragma unroll
        for (int j = 0; j < 4; j++) {
            re[j][0] += e.x * cc[j];  im[j][0] -= o.x * zc[j];
            re[j][1] += e.y * cc[j];  im[j][1] -= o.y * zc[j];
            float cn = K[j] * cc[j] - cp[j];  cp[j] = cc[j];  cc[j] = cn;
            float zn = K[j] * zc[j] - zp[j];  zp[j] = zc[j];  zc[j] = zn;
        }
    }
    const float SC = 1.f / 256.f;
#pragma unroll
    for (int j = 0; j < 4; j++) {
        int ky = ky0 + 8 * j;
#pragma unroll
        for (int r = 0; r < 2; r++)
            g_X1[(size_t)(bid * 64 + r0 + r) * 32 + ky] =
                make_float2(re[j][r] * SC, im[j][r] * SC);
    }
}

// ---------------- K2: DFT along x (256 -> 63), 4x folded, in-place fold ----------------
#define SMEM2 (256*32*8)
__global__ __launch_bounds__(256, 3) void sc_k2() {
    extern __shared__ float sm2[];
    float2* sX1 = (float2*)sm2;            // [x][ky] : 256*32
    int tid = threadIdx.x, bid = blockIdx.x;
    {
        const float4* src = (const float4*)(g_X1 + (size_t)bid * 8192);
        float4* dst = (float4*)sX1;
        for (int q = tid; q < 4096; q += 256) dst[q] = src[q];
    }
    __syncthreads();

    for (int e = tid; e < 63 * 32; e += 256) {
        int x = (e >> 5) + 1, ky = e & 31;
        float2 a = sX1[x * 32 + ky];
        float2 b = sX1[(256 - x) * 32 + ky];
        float2 c = sX1[(128 - x) * 32 + ky];
        float2 d = sX1[(128 + x) * 32 + ky];
        sX1[x * 32 + ky]         = make_float2(a.x + b.x + c.x + d.x, a.y + b.y + c.y + d.y);
        sX1[(256 - x) * 32 + ky] = make_float2(a.x + b.x - c.x - d.x, a.y + b.y - c.y - d.y);
        sX1[(128 - x) * 32 + ky] = make_float2(a.x - b.x + c.x - d.x, a.y - b.y + c.y - d.y);
        sX1[(128 + x) * 32 + ky] = make_float2(a.x - b.x - c.x + d.x, a.y - b.y - c.y + d.y);
    }
    __syncthreads();

    int ky = tid & 31, g = tid >> 5;
    int b = bid >> 6, i = bid & 63;
    int bi = b * 64 + i;
    int p = g & 1;
    float Cr0=0,Ci0=0,Sr0=0,Si0=0, Cr1=0,Ci1=0,Sr1=0,Si1=0;
    float Cr2=0,Ci2=0,Sr2=0,Si2=0, Cr3=0,Ci3=0,Sr3=0,Si3=0;
#pragma unroll 7
    for (int x = 1; x < 64; x++) {
        int eeIdx = (p ? (256 - x) : x) * 32 + ky;
        int ooIdx = (p ? (128 - x) : (128 + x)) * 32 + ky;
        float2 e = sX1[eeIdx];
        float2 o = sX1[ooIdx];
        const float2* twr = &g_tw1[(x - 1) * 32];
        float2 t0 = __ldg(twr + g);
        float2 t1 = __ldg(twr + g + 8);
        float2 t2 = __ldg(twr + g + 16);
        float2 t3 = __ldg(twr + g + 24);
        Cr0 += e.x*t0.x; Ci0 += e.y*t0.x; Sr0 += o.x*t0.y; Si0 += o.y*t0.y;
        Cr1 += e.x*t1.x; Ci1 += e.y*t1.x; Sr1 += o.x*t1.y; Si1 += o.y*t1.y;
        Cr2 += e.x*t2.x; Ci2 += e.y*t2.x; Sr2 += o.x*t2.y; Si2 += o.y*t2.y;
        Cr3 += e.x*t3.x; Ci3 += e.y*t3.x; Sr3 += o.x*t3.y; Si3 += o.y*t3.y;
    }
    float2 b0   = sX1[0 * 32 + ky];
    float2 b128 = sX1[128 * 32 + ky];
    float2 x64  = sX1[64 * 32 + ky];
    float2 x192 = sX1[192 * 32 + ky];
    float sgnB = p ? -1.f : 1.f;
    float baseR = b0.x + sgnB * b128.x, baseI = b0.y + sgnB * b128.y;
    float E64r = x64.x + x192.x, E64i = x64.y + x192.y;
    float O64r = x64.x - x192.x, O64i = x64.y - x192.y;
    float tpR, tpI, tmR, tmI;
    int gm4 = g & 3;
    if (!p) {
        float c4 = (gm4 == 0) ? 1.f : -1.f;
        tpR = tmR = c4 * E64r;  tpI = tmI = c4 * E64i;
    } else {
        float s4 = (gm4 == 1) ? 1.f : -1.f;
        tpR = s4 * O64i;  tpI = -s4 * O64r;
        tmR = -s4 * O64i; tmI = s4 * O64r;
    }
#define K2OUT(FQ, CR, CI, SR, SI)                                                        \
    g_X2[(size_t)((31 + (FQ)) * 32 + ky) * 1024 + bi] =                                  \
        make_float2(baseR + tpR + (CR) + (SI), baseI + tpI + (CI) - (SR));               \
    if ((FQ) > 0)                                                                        \
        g_X2[(size_t)((31 - (FQ)) * 32 + ky) * 1024 + bi] =                              \
            make_float2(baseR + tmR + (CR) - (SI), baseI + tmI + (CI) + (SR));
    K2OUT(g,      Cr0, Ci0, Sr0, Si0)
    K2OUT(g + 8,  Cr1, Ci1, Sr1, Si1)
    K2OUT(g + 16, Cr2, Ci2, Sr2, Si2)
    K2OUT(g + 24, Cr3, Ci3, Sr3, Si3)
#undef K2OUT
}

// ---------------- K3: channel mix, 4 (f,ky) tiles/block, 4b x 4o register blocking ----
__global__ __launch_bounds__(256, 4) void sc_k3() {
    __shared__ __align__(16) float2 sX[4 * 1024];
    int tid = threadIdx.x, bid = blockIdx.x;
    int tile = tid >> 6, t = tid & 63;
    int og = t & 15, bg = t >> 4;
    int fk = bid * 4 + tile;
    {
        float4* dst = (float4*)sX;
        for (int q = tid; q < 2048; q += 256) {
            int tq = q >> 9;
            dst[q] = *(const float4*)(g_X2 + (size_t)(bid * 4 + tq) * 1024 + (q & 511) * 2);
        }
    }
    __syncthreads();

    float ar[4][4], ai[4][4];
#pragma unroll
    for (int bb = 0; bb < 4; bb++)
#pragma unroll
        for (int oo = 0; oo < 4; oo++) { ar[bb][oo] = 0.f; ai[bb][oo] = 0.f; }

    const float2* Wbase = g_W + (size_t)fk * 4096 + og * 4;
    const float2* Xbase = sX + tile * 1024 + bg * 4 * 64;
#pragma unroll 4
    for (int i = 0; i < 64; i++) {
        float4 w01 = __ldg((const float4*)(Wbase + i * 64));
        float4 w23 = __ldg((const float4*)(Wbase + i * 64 + 2));
        float2 v0 = Xbase[i];
        float2 v1 = Xbase[64 + i];
        float2 v2 = Xbase[128 + i];
        float2 v3 = Xbase[192 + i];
#define CMAC(BB, V)                                                          \
        ar[BB][0] += V.x*w01.x - V.y*w01.y;  ai[BB][0] += V.x*w01.y + V.y*w01.x; \
        ar[BB][1] += V.x*w01.z - V.y*w01.w;  ai[BB][1] += V.x*w01.w + V.y*w01.z; \
        ar[BB][2] += V.x*w23.x - V.y*w23.y;  ai[BB][2] += V.x*w23.y + V.y*w23.x; \
        ar[BB][3] += V.x*w23.z - V.y*w23.w;  ai[BB][3] += V.x*w23.w + V.y*w23.z;
        CMAC(0, v0) CMAC(1, v1) CMAC(2, v2) CMAC(3, v3)
#undef CMAC
    }
    __syncthreads();
#pragma unroll
    for (int bb = 0; bb < 4; bb++)
#pragma unroll
        for (int oo = 0; oo < 4; oo++) {
            int bo = (bg * 4 + bb) * 64 + og * 4 + oo;
            sX[bo * 4 + tile] = make_float2(ar[bb][oo], ai[bb][oo]);
        }
    __syncthreads();
    int fk0 = bid * 4;
    for (int q = tid; q < 2048; q += 256) {
        int bo = q >> 1, half = q & 1;
        float4 val = *(const float4*)(sX + bo * 4 + half * 2);
        *(float4*)(g_X3 + (size_t)bo * 2016 + fk0 + half * 2) = val;
    }
}

// ---------------- K45: fused iDFT-x (63->256) + irfft-y (32->256) per (b,o) ----------
#define SMEM45 ((8192 + 2016 + 992 + 992 + 264) * 8)
__global__ __launch_bounds__(256, 2) void sc_k45(float* __restrict__ out) {
    extern __shared__ float smf[];
    float2* sYt  = (float2*)smf;            // [x(256)][ky(32)]
    float2* sX3  = sYt + 8192;              // 2016
    float2* sU   = sX3 + 2016;              // 992
    float2* sV   = sU + 992;                // 992
    float2* stab = sV + 992;                // 264
    int tid = threadIdx.x, bid = blockIdx.x;            // bid = b*64+o

    // ---- phase 1: K4 (iDFT along x), results to smem ----
    {
        const float4* src = (const float4*)(g_X3 + (size_t)bid * 2016);
        float4* dst = (float4*)sX3;
        for (int q = tid; q < 1008; q += 256) dst[q] = src[q];
        for (int q = tid; q < 264; q += 256) stab[q] = g_tab[q];
    }
    __syncthreads();
    for (int e = tid; e < 992; e += 256) {
        int ky = e & 31, fq = (e >> 5) + 1;
        float2 P = sX3[(31 + fq) * 32 + ky];
        float2 Q = sX3[(31 - fq) * 32 + ky];
        sU[e] = make_float2(P.x + Q.x, P.y + Q.y);
        sV[e] = make_float2(-(P.y - Q.y), P.x - Q.x);   // i*(P-Q)
    }
    __syncthreads();

    {
        int ky4 = (tid & 7) * 4, xs = tid >> 3;
        const float4* m = (const float4*)(sX3 + 31 * 32 + ky4);
        float4 m01 = m[0], m23 = m[1];
        for (int xi = 0; xi < 4; xi++) {
            int xx = xs + 32 * xi;                          // 0..127
            float c0 = m01.x, c1 = m01.y, c2 = m01.z, c3 = m01.w;
            float c4 = m23.x, c5 = m23.y, c6 = m23.z, c7 = m23.w;
            float s0 = 0, s1 = 0, s2 = 0, s3 = 0, s4 = 0, s5 = 0, s6 = 0, s7 = 0;
            int p = 0;
#pragma unroll 4
            for (int fq = 1; fq < 32; fq++) {
                p = (p + xx) & 255;
                float2 t = stab[tp(p)];
                const float4* up = (const float4*)(sU + (fq - 1) * 32 + ky4);
                const float4* vp = (const float4*)(sV + (fq - 1) * 32 + ky4);
                float4 u01 = up[0], u23 = up[1], v01 = vp[0], v23 = vp[1];
                c0 += t.x * u01.x;  s0 += t.y * v01.x;
                c1 += t.x * u01.y;  s1 += t.y * v01.y;
                c2 += t.x * u01.z;  s2 += t.y * v01.z;
                c3 += t.x * u01.w;  s3 += t.y * v01.w;
                c4 += t.x * u23.x;  s4 += t.y * v23.x;
                c5 += t.x * u23.y;  s5 += t.y * v23.y;
                c6 += t.x * u23.z;  s6 += t.y * v23.z;
                c7 += t.x * u23.w;  s7 += t.y * v23.w;
            }
            float4* o1 = (float4*)(sYt + xx * 32 + ky4);
            o1[0] = make_float4(c0 + s0, c1 + s1, c2 + s2, c3 + s3);
            o1[1] = make_float4(c4 + s4, c5 + s5, c6 + s6, c7 + s7);
            if (xx > 0) {
                float4* o2 = (float4*)(sYt + (256 - xx) * 32 + ky4);
                o2[0] = make_float4(c0 - s0, c1 - s1, c2 - s2, c3 - s3);
                o2[1] = make_float4(c4 - s4, c5 - s5, c6 - s6, c7 - s7);
            }
        }
        if (tid < 32) {
            int ky = tid;
            float2 acc = sX3[31 * 32 + ky];
#pragma unroll 4
            for (int fq = 1; fq < 32; fq++) {
                float2 u = sU[(fq - 1) * 32 + ky];
                float sg = (fq & 1) ? -1.f : 1.f;
                acc.x += sg * u.x;  acc.y += sg * u.y;
            }
            sYt[128 * 32 + ky] = acc;
        }
    }
    __syncthreads();

    // ---- phase 2: K5 (irfft along y), 8 row-groups of 32 ----
    int l = tid & 31, w = tid >> 5;
    int r0 = 4 * w;
    float2 tA = __ldg(&g_tw1[l]);
    const float R45 = 0.70710678118654752f;
    float cB1 = (tA.x - tA.y) * R45;
    float sB1 = (tA.x + tA.y) * R45;
    float KA = 2.f * tA.x, KB = 2.f * cB1;
    const float SC1 = 1.f / 256.f, SC2 = 2.f / 256.f;

    for (int rg = 0; rg < 8; rg++) {
        const float2* sY = sYt + rg * 1024;     // [row(32)][ky(32)]
        float cAc = 1.f, cAp = tA.x;
        float zAc = 0.f, zAp = -tA.y;
        float cBc = 1.f, cBp = cB1;
        float zBc = 0.f, zBp = -sB1;

        float Ae0[4]={0,0,0,0}, Se0[4]={0,0,0,0}, Ao0[4]={0,0,0,0}, So0[4]={0,0,0,0};
        float Ae1[4]={0,0,0,0}, Se1[4]={0,0,0,0}, Ao1[4]={0,0,0,0}, So1[4]={0,0,0,0};

#pragma unroll 4
        for (int kp = 0; kp < 16; kp++) {
            float n;
            n = KA * cAc - cAp;  cAp = cAc;  cAc = n;
            n = KA * zAc - zAp;  zAp = zAc;  zAc = n;
            n = KB * cBc - cBp;  cBp = cBc;  cBc = n;
            n = KB * zBc - zBp;  zBp = zBc;  zBc = n;
            int kyo = 2 * kp + 1;
#pragma unroll
            for (int r = 0; r < 4; r++) {
                float2 v = sY[(r0 + r) * 32 + kyo];
                Ao0[r] += v.x * cAc;  So0[r] += v.y * zAc;
                Ao1[r] += v.x * cBc;  So1[r] += v.y * zBc;
            }
            if (kp < 15) {
                n = KA * cAc - cAp;  cAp = cAc;  cAc = n;
                n = KA * zAc - zAp;  zAp = zAc;  zAc = n;
                n = KB * cBc - cBp;  cBp = cBc;  cBc = n;
                n = KB * zBc - zBp;  zBp = zBc;  zBc = n;
                int kye = 2 * kp + 2;
#pragma unroll
                for (int r = 0; r < 4; r++) {
                    float2 v = sY[(r0 + r) * 32 + kye];
                    Ae0[r] += v.x * cAc;  Se0[r] += v.y * zAc;
                    Ae1[r] += v.x * cBc;  Se1[r] += v.y * zBc;
                }
            }
        }

#pragma unroll
        for (int r = 0; r < 4; r++) {
            size_t ob = ((size_t)bid * 256 + rg * 32 + r0 + r) * 256;
            float bx = sY[(r0 + r) * 32].x * SC1;
            float a  = SC2 * (Ae0[r] + Ao0[r]) + bx;
            float s  = SC2 * (Se0[r] + So0[r]);
            float am = SC2 * (Ae0[r] - Ao0[r]) + bx;
            float sm = SC2 * (Se0[r] - So0[r]);
            out[ob + l]       = a - s;
            out[ob + 128 - l] = am + sm;
            if (l > 0) {
                out[ob + 256 - l] = a + s;
                out[ob + 128 + l] = am - sm;
            }
            float a1  = SC2 * (Ae1[r] + Ao1[r]) + bx;
            float s1  = SC2 * (Se1[r] + So1[r]);
            float am1 = SC2 * (Ae1[r] - Ao1[r]) + bx;
            float sm1 = SC2 * (Se1[r] - So1[r]);
            out[ob + 32 + l]  = a1 - s1;
            out[ob + 224 - l] = a1 + s1;
            out[ob + 96 - l]  = am1 + sm1;
            out[ob + 160 + l] = am1 - sm1;
        }
        // tail t = 64 / 192
        {
            int ky = l;
            float sc = (ky == 0) ? SC1 : SC2;
            int m4 = ky & 3;
            float c64 = (m4 == 0) ? sc : (m4 == 2 ? -sc : 0.f);
            float s64 = (m4 == 1) ? sc : (m4 == 3 ? -sc : 0.f);
#pragma unroll
            for (int r = 0; r < 4; r++) {
                float2 v = sY[(r0 + r) * 32 + ky];
                float p = v.x * c64 - v.y * s64;
                float q = v.x * c64 + v.y * s64;
#pragma unroll
                for (int off = 16; off; off >>= 1) {
                    p += __shfl_xor_sync(0xFFFFFFFFu, p, off);
                    q += __shfl_xor_sync(0xFFFFFFFFu, q, off);
                }
                if (l == 0) {
                    size_t ob = ((size_t)bid * 256 + rg * 32 + r0 + r) * 256;
                    out[ob + 64]  = p;
                    out[ob + 192] = q;
                }
            }
        }
    }
}

// ---------------- launch ----------------
extern "C" void kernel_launch(void* const* d_in, const int* in_sizes, int n_in,
                              void* d_out, int out_size) {
    const float* x   = (const float*)d_in[0];
    const float* y0r = (const float*)d_in[1];
    const float* y0i = (const float*)d_in[2];
    const float* ypr = (const float*)d_in[3];
    const float* ypi = (const float*)d_in[4];
    const float* w00 = (const float*)d_in[5];
    float* out = (float*)d_out;

    cudaFuncSetAttribute(sc_k1, cudaFuncAttributeMaxDynamicSharedMemorySize, SMEM1);
    cudaFuncSetAttribute(sc_k2, cudaFuncAttributeMaxDynamicSharedMemorySize, SMEM2);
    cudaFuncSetAttribute(sc_k45, cudaFuncAttributeMaxDynamicSharedMemorySize, SMEM45);

    sc_tabs<<<9, 256>>>();
    sc_build_w0<<<(63 * 4096 + 255) / 256, 256>>>(y0r, y0i, w00);
    sc_build_wt<<<dim3(62, 128), dim3(32, 8)>>>(ypr, ypi);
    sc_k1<<<4096, 256, SMEM1>>>(x);
    sc_k2<<<1024, 256, SMEM2>>>();
    sc_k3<<<504, 256>>>();
    sc_k45<<<1024, 256, SMEM45>>>(out);
}

// round 8
// speedup vs baseline: 2.6232x; 1.0209x over previous
#include <cuda_runtime.h>
#include <cstdint>

// Problem dims (fixed): B=16, Ci=Co=64, S=256, m1=m2=32
// ---------------- device scratch (no allocs allowed) ----------------
__device__ __align__(16) float2 g_tab[264];                       // padded cos/sin table (K45)
__device__ __align__(16) float2 g_tw1[63*32];                     // [s-1][ky] twiddles
__device__ __align__(16) float2 g_W [63*32*64*64];                // [f][ky][i][o]
__device__ __align__(16) float2 g_X2[63*32*16*64];                // [f][ky][b][i]
__device__ __align__(16) float2 g_X3[16*64*63*32];                // [b][o][f][ky]

__device__ __forceinline__ int tp(int i) { return i + (i >> 5); }

// ---------------- init: all tables ----------------
__global__ void sc_tabs() {
    int t = blockIdx.x * 256 + threadIdx.x;
    if (t < 264) {
        int k = t / 33;
        int idx = t - k;
        float ang = (float)(6.283185307179586 * (double)idx / 256.0);
        g_tab[t] = make_float2(cosf(ang), sinf(ang));
    }
    int e1 = t - 264;
    if (e1 >= 0 && e1 < 63 * 32) {
        int s = (e1 >> 5) + 1, ky = e1 & 31;           // s = 1..63
        double ang = 6.283185307179586 * (double)((ky * s) % 256) / 256.0;
        g_tw1[e1] = make_float2((float)cos(ang), (float)sin(ang));
    }
}

// ---------------- build W: ky=0 plane ----------------
__global__ void sc_build_w0(const float* __restrict__ y0r, const float* __restrict__ y0i,
                            const float* __restrict__ w00) {
    int t = blockIdx.x * 256 + threadIdx.x;
    if (t >= 63 * 4096) return;
    int io = t & 4095;
    int f  = t >> 12;
    float wr, wi;
    if (f < 31)       { wr = y0r[io * 31 + f];        wi = y0i[io * 31 + f]; }
    else if (f == 31) { wr = w00[io];                 wi = 0.f; }
    else              { wr = y0r[io * 31 + (62 - f)]; wi = -y0i[io * 31 + (62 - f)]; }
    g_W[(size_t)(f * 32) * 4096 + io] = make_float2(wr, wi);
}

// ---------------- build W: ky>=1 planes via tiled transpose ----------------
__global__ void sc_build_wt(const float* __restrict__ ypr, const float* __restrict__ ypi) {
    __shared__ float2 tile[32][33];
    int tx = threadIdx.x, ty = threadIdx.y;        // 32 x 8
    int fk0 = blockIdx.x * 32, io0 = blockIdx.y * 32;
#pragma unroll
    for (int k = 0; k < 4; k++) {
        int io = io0 + ty + 8 * k;
        int fk = fk0 + tx;
        if (fk < 1953)
            tile[ty + 8 * k][tx] = make_float2(ypr[(size_t)io * 1953 + fk],
                                               ypi[(size_t)io * 1953 + fk]);
    }
    __syncthreads();
#pragma unroll
    for (int k = 0; k < 4; k++) {
        int fk = fk0 + ty + 8 * k;
        if (fk < 1953) {
            int f  = fk / 31;
            int ky = fk - f * 31 + 1;
            g_W[(size_t)(f * 32 + ky) * 4096 + io0 + tx] = tile[tx][ty + 8 * k];
        }
    }
}

// ---------------- K12: fused DFT-y + DFT-x per (b,i) image ----------------
// Phase 1 (warp-local): 16 warps x 2 iters, each warp folds+DFTs 8 rows -> sX1 tile.
// Phase 2: K2 logic (4x fold + 63-term DFT-x) from the smem tile; 2 freqs/thread.
#define SMEM12 ((4*64*130 + 256*4) * 4 + 256*32*8)
__global__ __launch_bounds__(512, 1) void sc_k12(const float* __restrict__ x) {
    extern __shared__ float sm12[];
    float* sEp = sm12;                    // [s(0..63)][slot(130 pad, 128 used)]
    float* sEm = sEp + 64 * 130;
    float* sOp = sEm + 64 * 130;
    float* sOm = sOp + 64 * 130;
    float* sbase = sOm + 64 * 130;        // [row(256)][4]
    float2* sX1 = (float2*)(sbase + 1024);// [x(256)][ky(32)]
    int tid = threadIdx.x, bid = blockIdx.x;      // bid = b*64 + i
    int lane = tid & 31, w = tid >> 5;            // w = 0..15
    const float* gx = x + (size_t)bid * 65536;
    int sp = (32 - lane) & 31;

    // ---- phase 1: DFT along y, warp-local ----
    int ky0 = lane & 7, rp2 = lane >> 3;
    int slot0 = 8 * w + 2 * rp2;
    int p1q = ky0 & 1;
    float sgn1 = p1q ? -1.f : 1.f;
    int m41 = ky0 & 3;
    float c64a = (m41 == 0) ? 1.f : (m41 == 2 ? -1.f : 0.f);
    float s64a = (m41 == 1) ? 1.f : (m41 == 3 ? -1.f : 0.f);
    const float* EE = p1q ? sEm : sEp;
    const float* OO = p1q ? sOp : sOm;
    float Kk[4], t1x[4], t1y[4];
#pragma unroll
    for (int j = 0; j < 4; j++) {
        float2 t1 = __ldg(&g_tw1[ky0 + 8 * j]);
        Kk[j] = 2.f * t1.x;  t1x[j] = t1.x;  t1y[j] = t1.y;
    }

    for (int it = 0; it < 2; it++) {
        int rowbase = 8 * w + 128 * it;
#pragma unroll
        for (int r = 0; r < 8; r++) {
            int row = rowbase + r;
            int slot = 8 * w + r;
            const float* rp = gx + row * 256;
            float v[8];
#pragma unroll
            for (int k = 0; k < 8; k++) v[k] = rp[lane + 32 * k];
            float E1[4], O1[4];
#pragma unroll
            for (int k = 0; k < 4; k++) {
                float p1 = __shfl_sync(0xFFFFFFFFu, v[7 - k], sp);
                if (lane == 0) p1 = v[(8 - k) & 7];
                E1[k] = v[k] + p1;
                O1[k] = v[k] - p1;
            }
#pragma unroll
            for (int k = 0; k < 2; k++) {
                int c = lane + 32 * k;
                float qe = __shfl_sync(0xFFFFFFFFu, E1[3 - k], sp);
                float qo = __shfl_sync(0xFFFFFFFFu, O1[3 - k], sp);
                if (k == 1 && lane == 0) { qe = E1[3]; qo = O1[3]; }
                float ep = E1[k] + qe, em = E1[k] - qe;
                float op = O1[k] + qo, om = O1[k] - qo;
                if (c >= 1 && c <= 63) {
                    sEp[c * 130 + slot] = ep;
                    sEm[c * 130 + slot] = em;
                    sOp[c * 130 + slot] = op;
                    sOm[c * 130 + slot] = om;
                }
            }
            if (lane == 0) {
                sbase[row * 4 + 0] = v[0];
                sbase[row * 4 + 1] = v[4];
                sbase[row * 4 + 2] = v[2] + v[6];
                sbase[row * 4 + 3] = v[2] - v[6];
            }
        }
        __syncwarp();

        int row0 = slot0 + 128 * it;
        float cp[4], cc[4], zp[4], zc[4];
#pragma unroll
        for (int j = 0; j < 4; j++) {
            cp[j] = 1.f;  cc[j] = t1x[j];
            zp[j] = 0.f;  zc[j] = t1y[j];
        }
        float re[4][2], im[4][2];
        {
            const float* b0 = sbase + row0 * 4;
            const float* b1 = sbase + (row0 + 1) * 4;
            float base0 = b0[0] + sgn1 * b0[1] + c64a * b0[2];
            float base1 = b1[0] + sgn1 * b1[1] + c64a * b1[2];
            float imb0 = -s64a * b0[3];
            float imb1 = -s64a * b1[3];
#pragma unroll
            for (int j = 0; j < 4; j++) {
                re[j][0] = base0;  re[j][1] = base1;
                im[j][0] = imb0;   im[j][1] = imb1;
            }
        }
#pragma unroll 7
        for (int s = 1; s < 64; s++) {
            float2 e = *(const float2*)(EE + s * 130 + slot0);
            float2 o = *(const float2*)(OO + s * 130 + slot0);
#pragma unroll
            for (int j = 0; j < 4; j++) {
                re[j][0] += e.x * cc[j];  im[j][0] -= o.x * zc[j];
                re[j][1] += e.y * cc[j];  im[j][1] -= o.y * zc[j];
                float cn = Kk[j] * cc[j] - cp[j];  cp[j] = cc[j];  cc[j] = cn;
                float zn = Kk[j] * zc[j] - zp[j];  zp[j] = zc[j];  zc[j] = zn;
            }
        }
        const float SC = 1.f / 256.f;
#pragma unroll
        for (int j = 0; j < 4; j++) {
            int ky = ky0 + 8 * j;
#pragma unroll
            for (int r = 0; r < 2; r++)
                sX1[(row0 + r) * 32 + ky] = make_float2(re[j][r] * SC, im[j][r] * SC);
        }
        __syncwarp();      // protect fold-slot reuse across iters
    }
    __syncthreads();

    // ---- phase 2: 4x fold in x (in place) ----
    for (int e = tid; e < 63 * 32; e += 512) {
        int xx = (e >> 5) + 1, ky = e & 31;
        float2 a = sX1[xx * 32 + ky];
        float2 b = sX1[(256 - xx) * 32 + ky];
        float2 c = sX1[(128 - xx) * 32 + ky];
        float2 d = sX1[(128 + xx) * 32 + ky];
        sX1[xx * 32 + ky]         = make_float2(a.x + b.x + c.x + d.x, a.y + b.y + c.y + d.y);
        sX1[(256 - xx) * 32 + ky] = make_float2(a.x + b.x - c.x - d.x, a.y + b.y - c.y - d.y);
        sX1[(128 - xx) * 32 + ky] = make_float2(a.x - b.x + c.x - d.x, a.y - b.y + c.y - d.y);
        sX1[(128 + xx) * 32 + ky] = make_float2(a.x - b.x - c.x + d.x, a.y - b.y - c.y + d.y);
    }
    __syncthreads();

    // ---- phase 2: DFT along x (63 terms), 2 freqs per thread ----
    int ky = tid & 31, g = tid >> 5;          // g = 0..15, freqs {g, g+16}
    int bi = bid;
    int p = g & 1;
    float Cr0=0,Ci0=0,Sr0=0,Si0=0, Cr1=0,Ci1=0,Sr1=0,Si1=0;
#pragma unroll 7
    for (int xx = 1; xx < 64; xx++) {
        int eeIdx = (p ? (256 - xx) : xx) * 32 + ky;
        int ooIdx = (p ? (128 - xx) : (128 + xx)) * 32 + ky;
        float2 e = sX1[eeIdx];
        float2 o = sX1[ooIdx];
        const float2* twr = &g_tw1[(xx - 1) * 32];
        float2 t0 = __ldg(twr + g);
        float2 t1 = __ldg(twr + g + 16);
        Cr0 += e.x*t0.x; Ci0 += e.y*t0.x; Sr0 += o.x*t0.y; Si0 += o.y*t0.y;
        Cr1 += e.x*t1.x; Ci1 += e.y*t1.x; Sr1 += o.x*t1.y; Si1 += o.y*t1.y;
    }
    float2 b0   = sX1[0 * 32 + ky];
    float2 b128 = sX1[128 * 32 + ky];
    float2 x64  = sX1[64 * 32 + ky];
    float2 x192 = sX1[192 * 32 + ky];
    float sgnB = p ? -1.f : 1.f;
    float baseR = b0.x + sgnB * b128.x, baseI = b0.y + sgnB * b128.y;
    float E64r = x64.x + x192.x, E64i = x64.y + x192.y;
    float O64r = x64.x - x192.x, O64i = x64.y - x192.y;
    float tpR, tpI, tmR, tmI;
    int gm4 = g & 3;                           // (g+16)&3 == g&3
    if (!p) {
        float c4 = (gm4 == 0) ? 1.f : -1.f;
        tpR = tmR = c4 * E64r;  tpI = tmI = c4 * E64i;
    } else {
        float s4 = (gm4 == 1) ? 1.f : -1.f;
        tpR = s4 * O64i;  tpI = -s4 * O64r;
        tmR = -s4 * O64i; tmI = s4 * O64r;
    }
#define K2OUT(FQ, CR, CI, SR, SI)                                                        \
    g_X2[(size_t)((31 + (FQ)) * 32 + ky) * 1024 + bi] =                                  \
        make_float2(baseR + tpR + (CR) + (SI), baseI + tpI + (CI) - (SR));               \
    if ((FQ) > 0)                                                                        \
        g_X2[(size_t)((31 - (FQ)) * 32 + ky) * 1024 + bi] =                              \
            make_float2(baseR + tmR + (CR) - (SI), baseI + tmI + (CI) + (SR));
    K2OUT(g,      Cr0, Ci0, Sr0, Si0)
    K2OUT(g + 16, Cr1, Ci1, Sr1, Si1)
#undef K2OUT
}

// ---------------- K3: channel mix, 4 (f,ky) tiles/block, 4b x 4o register blocking ----
__global__ __launch_bounds__(256, 4) void sc_k3() {
    __shared__ __align__(16) float2 sX[4 * 1024];
    int tid = threadIdx.x, bid = blockIdx.x;
    int tile = tid >> 6, t = tid & 63;
    int og = t & 15, bg = t >> 4;
    int fk = bid * 4 + tile;
    {
        float4* dst = (float4*)sX;
        for (int q = tid; q < 2048; q += 256) {
            int tq = q >> 9;
            dst[q] = *(const float4*)(g_X2 + (size_t)(bid * 4 + tq) * 1024 + (q & 511) * 2);
        }
    }
    __syncthreads();

    float ar[4][4], ai[4][4];
#pragma unroll
    for (int bb = 0; bb < 4; bb++)
#pragma unroll
        for (int oo = 0; oo < 4; oo++) { ar[bb][oo] = 0.f; ai[bb][oo] = 0.f; }

    const float2* Wbase = g_W + (size_t)fk * 4096 + og * 4;
    const float2* Xbase = sX + tile * 1024 + bg * 4 * 64;
#pragma unroll 4
    for (int i = 0; i < 64; i++) {
        float4 w01 = __ldg((const float4*)(Wbase + i * 64));
        float4 w23 = __ldg((const float4*)(Wbase + i * 64 + 2));
        float2 v0 = Xbase[i];
        float2 v1 = Xbase[64 + i];
        float2 v2 = Xbase[128 + i];
        float2 v3 = Xbase[192 + i];
#define CMAC(BB, V)                                                          \
        ar[BB][0] += V.x*w01.x - V.y*w01.y;  ai[BB][0] += V.x*w01.y + V.y*w01.x; \
        ar[BB][1] += V.x*w01.z - V.y*w01.w;  ai[BB][1] += V.x*w01.w + V.y*w01.z; \
        ar[BB][2] += V.x*w23.x - V.y*w23.y;  ai[BB][2] += V.x*w23.y + V.y*w23.x; \
        ar[BB][3] += V.x*w23.z - V.y*w23.w;  ai[BB][3] += V.x*w23.w + V.y*w23.z;
        CMAC(0, v0) CMAC(1, v1) CMAC(2, v2) CMAC(3, v3)
#undef CMAC
    }
    __syncthreads();
#pragma unroll
    for (int bb = 0; bb < 4; bb++)
#pragma unroll
        for (int oo = 0; oo < 4; oo++) {
            int bo = (bg * 4 + bb) * 64 + og * 4 + oo;
            sX[bo * 4 + tile] = make_float2(ar[bb][oo], ai[bb][oo]);
        }
    __syncthreads();
    int fk0 = bid * 4;
    for (int q = tid; q < 2048; q += 256) {
        int bo = q >> 1, half = q & 1;
        float4 val = *(const float4*)(sX + bo * 4 + half * 2);
        *(float4*)(g_X3 + (size_t)bo * 2016 + fk0 + half * 2) = val;
    }
}

// ---------------- K45: fused iDFT-x (63->256) + irfft-y (32->256) per (b,o) ----------
#define SMEM45 ((8192 + 2016 + 992 + 992 + 264) * 8)
__global__ __launch_bounds__(256, 2) void sc_k45(float* __restrict__ out) {
    extern __shared__ float smf[];
    float2* sYt  = (float2*)smf;            // [x(256)][ky(32)]
    float2* sX3  = sYt + 8192;              // 2016
    float2* sU   = sX3 + 2016;              // 992
    float2* sV   = sU + 992;                // 992
    float2* stab = sV + 992;                // 264
    int tid = threadIdx.x, bid = blockIdx.x;            // bid = b*64+o

    {
        const float4* src = (const float4*)(g_X3 + (size_t)bid * 2016);
        float4* dst = (float4*)sX3;
        for (int q = tid; q < 1008; q += 256) dst[q] = src[q];
        for (int q = tid; q < 264; q += 256) stab[q] = g_tab[q];
    }
    __syncthreads();
    for (int e = tid; e < 992; e += 256) {
        int ky = e & 31, fq = (e >> 5) + 1;
        float2 P = sX3[(31 + fq) * 32 + ky];
        float2 Q = sX3[(31 - fq) * 32 + ky];
        sU[e] = make_float2(P.x + Q.x, P.y + Q.y);
        sV[e] = make_float2(-(P.y - Q.y), P.x - Q.x);   // i*(P-Q)
    }
    __syncthreads();

    {
        int ky4 = (tid & 7) * 4, xs = tid >> 3;
        const float4* m = (const float4*)(sX3 + 31 * 32 + ky4);
        float4 m01 = m[0], m23 = m[1];
        for (int xi = 0; xi < 4; xi++) {
            int xx = xs + 32 * xi;
            float c0 = m01.x, c1 = m01.y, c2 = m01.z, c3 = m01.w;
            float c4 = m23.x, c5 = m23.y, c6 = m23.z, c7 = m23.w;
            float s0 = 0, s1 = 0, s2 = 0, s3 = 0, s4 = 0, s5 = 0, s6 = 0, s7 = 0;
            int p = 0;
#pragma unroll 4
            for (int fq = 1; fq < 32; fq++) {
                p = (p + xx) & 255;
                float2 t = stab[tp(p)];
                const float4* up = (const float4*)(sU + (fq - 1) * 32 + ky4);
                const float4* vp = (const float4*)(sV + (fq - 1) * 32 + ky4);
                float4 u01 = up[0], u23 = up[1], v01 = vp[0], v23 = vp[1];
                c0 += t.x * u01.x;  s0 += t.y * v01.x;
                c1 += t.x * u01.y;  s1 += t.y * v01.y;
                c2 += t.x * u01.z;  s2 += t.y * v01.z;
                c3 += t.x * u01.w;  s3 += t.y * v01.w;
                c4 += t.x * u23.x;  s4 += t.y * v23.x;
                c5 += t.x * u23.y;  s5 += t.y * v23.y;
                c6 += t.x * u23.z;  s6 += t.y * v23.z;
                c7 += t.x * u23.w;  s7 += t.y * v23.w;
            }
            float4* o1 = (float4*)(sYt + xx * 32 + ky4);
            o1[0] = make_float4(c0 + s0, c1 + s1, c2 + s2, c3 + s3);
            o1[1] = make_float4(c4 + s4, c5 + s5, c6 + s6, c7 + s7);
            if (xx > 0) {
                float4* o2 = (float4*)(sYt + (256 - xx) * 32 + ky4);
                o2[0] = make_float4(c0 - s0, c1 - s1, c2 - s2, c3 - s3);
                o2[1] = make_float4(c4 - s4, c5 - s5, c6 - s6, c7 - s7);
            }
        }
        if (tid < 32) {
            int ky = tid;
            float2 acc = sX3[31 * 32 + ky];
#pragma unroll 4
            for (int fq = 1; fq < 32; fq++) {
                float2 u = sU[(fq - 1) * 32 + ky];
                float sg = (fq & 1) ? -1.f : 1.f;
                acc.x += sg * u.x;  acc.y += sg * u.y;
            }
            sYt[128 * 32 + ky] = acc;
        }
    }
    __syncthreads();

    int l = tid & 31, w = tid >> 5;
    int r0 = 4 * w;
    float2 tA = __ldg(&g_tw1[l]);
    const float R45 = 0.70710678118654752f;
    float cB1 = (tA.x - tA.y) * R45;
    float sB1 = (tA.x + tA.y) * R45;
    float KA = 2.f * tA.x, KB = 2.f * cB1;
    const float SC1 = 1.f / 256.f, SC2 = 2.f / 256.f;

    for (int rg = 0; rg < 8; rg++) {
        const float2* sY = sYt + rg * 1024;
        float cAc = 1.f, cAp = tA.x;
        float zAc = 0.f, zAp = -tA.y;
        float cBc = 1.f, cBp = cB1;
        float zBc = 0.f, zBp = -sB1;

        float Ae0[4]={0,0,0,0}, Se0[4]={0,0,0,0}, Ao0[4]={0,0,0,0}, So0[4]={0,0,0,0};
        float Ae1[4]={0,0,0,0}, Se1[4]={0,0,0,0}, Ao1[4]={0,0,0,0}, So1[4]={0,0,0,0};

#pragma unroll 4
        for (int kp = 0; kp < 16; kp++) {
            float n;
            n = KA * cAc - cAp;  cAp = cAc;  cAc = n;
            n = KA * zAc - zAp;  zAp = zAc;  zAc = n;
            n = KB * cBc - cBp;  cBp = cBc;  cBc = n;
            n = KB * zBc - zBp;  zBp = zBc;  zBc = n;
            int kyo = 2 * kp + 1;
#pragma unroll
            for (int r = 0; r < 4; r++) {
                float2 v = sY[(r0 + r) * 32 + kyo];
                Ao0[r] += v.x * cAc;  So0[r] += v.y * zAc;
                Ao1[r] += v.x * cBc;  So1[r] += v.y * zBc;
            }
            if (kp < 15) {
                n = KA * cAc - cAp;  cAp = cAc;  cAc = n;
                n = KA * zAc - zAp;  zAp = zAc;  zAc = n;
                n = KB * cBc - cBp;  cBp = cBc;  cBc = n;
                n = KB * zBc - zBp;  zBp = zBc;  zBc = n;
                int kye = 2 * kp + 2;
#pragma unroll
                for (int r = 0; r < 4; r++) {
                    float2 v = sY[(r0 + r) * 32 + kye];
                    Ae0[r] += v.x * cAc;  Se0[r] += v.y * zAc;
                    Ae1[r] += v.x * cBc;  Se1[r] += v.y * zBc;
                }
            }
        }

#pragma unroll
        for (int r = 0; r < 4; r++) {
            size_t ob = ((size_t)bid * 256 + rg * 32 + r0 + r) * 256;
            float bx = sY[(r0 + r) * 32].x * SC1;
            float a  = SC2 * (Ae0[r] + Ao0[r]) + bx;
            float s  = SC2 * (Se0[r] + So0[r]);
            float am = SC2 * (Ae0[r] - Ao0[r]) + bx;
            float sm = SC2 * (Se0[r] - So0[r]);
            out[ob + l]       = a - s;
            out[ob + 128 - l] = am + sm;
            if (l > 0) {
                out[ob + 256 - l] = a + s;
                out[ob + 128 + l] = am - sm;
            }
            float a1  = SC2 * (Ae1[r] + Ao1[r]) + bx;
            float s1  = SC2 * (Se1[r] + So1[r]);
            float am1 = SC2 * (Ae1[r] - Ao1[r]) + bx;
            float sm1 = SC2 * (Se1[r] - So1[r]);
            out[ob + 32 + l]  = a1 - s1;
            out[ob + 224 - l] = a1 + s1;
            out[ob + 96 - l]  = am1 + sm1;
            out[ob + 160 + l] = am1 - sm1;
        }
        {
            int ky = l;
            float sc = (ky == 0) ? SC1 : SC2;
            int m4 = ky & 3;
            float c64 = (m4 == 0) ? sc : (m4 == 2 ? -sc : 0.f);
            float s64 = (m4 == 1) ? sc : (m4 == 3 ? -sc : 0.f);
#pragma unroll
            for (int r = 0; r < 4; r++) {
                float2 v = sY[(r0 + r) * 32 + ky];
                float p = v.x * c64 - v.y * s64;
                float q = v.x * c64 + v.y * s64;
#pragma unroll
                for (int off = 16; off; off >>= 1) {
                    p += __shfl_xor_sync(0xFFFFFFFFu, p, off);
                    q += __shfl_xor_sync(0xFFFFFFFFu, q, off);
                }
                if (l == 0) {
                    size_t ob = ((size_t)bid * 256 + rg * 32 + r0 + r) * 256;
                    out[ob + 64]  = p;
                    out[ob + 192] = q;
                }
            }
        }
    }
}

// ---------------- launch ----------------
extern "C" void kernel_launch(void* const* d_in, const int* in_sizes, int n_in,
                              void* d_out, int out_size) {
    const float* x   = (const float*)d_in[0];
    const float* y0r = (const float*)d_in[1];
    const float* y0i = (const float*)d_in[2];
    const float* ypr = (const float*)d_in[3];
    const float* ypi = (const float*)d_in[4];
    const float* w00 = (const float*)d_in[5];
    float* out = (float*)d_out;

    cudaFuncSetAttribute(sc_k12, cudaFuncAttributeMaxDynamicSharedMemorySize, SMEM12);
    cudaFuncSetAttribute(sc_k45, cudaFuncAttributeMaxDynamicSharedMemorySize, SMEM45);

    sc_tabs<<<9, 256>>>();
    sc_build_w0<<<(63 * 4096 + 255) / 256, 256>>>(y0r, y0i, w00);
    sc_build_wt<<<dim3(62, 128), dim3(32, 8)>>>(ypr, ypi);
    sc_k12<<<1024, 512, SMEM12>>>(x);
    sc_k3<<<504, 256>>>();
    sc_k45<<<1024, 256, SMEM45>>>(out);
}